// round 14
// baseline (speedup 1.0000x reference)
#include <cuda_runtime.h>
#include <cuda_bf16.h>
#include <mma.h>
#include <math.h>

using namespace nvcuda;

// ---------------- problem constants ----------------
#define EMB      1024
#define N_HEADS  16
#define N_KV     4
#define HEAD_DIM 128
#define N_EXP    8
#define TOP_K    2
#define MOE_HID  1024
#define BATCH    2
#define SEQ      2048
#define T_TOK    (BATCH*SEQ)          // 4096
#define QDIM     (N_HEADS*HEAD_DIM)   // 2048
#define KVDIM    (N_KV*HEAD_DIM)      // 512
#define QKVDIM   (QDIM + 2*KVDIM)     // 3072
#define N_SLOT   (T_TOK*TOP_K)        // 8192
#define EPSV     1e-6f

typedef __nv_bfloat16 bf16;

// ---------------- scratch (device globals; no allocation allowed) ----------------
__device__ bf16  g_h1hi[T_TOK*EMB],  g_h1lo[T_TOK*EMB];
__device__ float g_qkv[T_TOK*QKVDIM];
__device__ bf16  g_qhi[T_TOK*QDIM],  g_qlo[T_TOK*QDIM];
__device__ bf16  g_khi[T_TOK*KVDIM], g_klo[T_TOK*KVDIM];
__device__ bf16  g_vhi[T_TOK*KVDIM], g_vlo[T_TOK*KVDIM];
__device__ bf16  g_ctxhi[T_TOK*QDIM], g_ctxlo[T_TOK*QDIM];
__device__ float g_x1[T_TOK*EMB];
__device__ float g_h2[T_TOK*EMB];
__device__ bf16  g_h2hi[T_TOK*EMB],  g_h2lo[T_TOK*EMB];
__device__ bf16  g_acthi[N_SLOT*MOE_HID], g_actlo[N_SLOT*MOE_HID];
__device__ float g_ropecos[SEQ*64], g_ropesin[SEQ*64];
__device__ int   g_topk_idx[N_SLOT];
__device__ float g_topk_w[N_SLOT];
__device__ int   g_counts[N_EXP];
__device__ int   g_off[N_EXP];
__device__ int   g_cursor[N_EXP];
__device__ int   g_slot_token[N_SLOT];
__device__ float g_slot_w[N_SLOT];

// ---------------- bf16 hi/lo split helpers ----------------
__device__ __forceinline__ void split_bf16(float x, bf16& hi, bf16& lo) {
    hi = __float2bfloat16(x);
    lo = __float2bfloat16(x - __bfloat162float(hi));
}
__device__ __forceinline__ void split_store4(float4 v, bf16* hi, bf16* lo, long long idx) {
    bf16 h0,l0,h1,l1,h2,l2,h3,l3;
    split_bf16(v.x,h0,l0); split_bf16(v.y,h1,l1);
    split_bf16(v.z,h2,l2); split_bf16(v.w,h3,l3);
    __nv_bfloat162 hh0 = {h0,h1}, hh1 = {h2,h3};
    __nv_bfloat162 ll0 = {l0,l1}, ll1 = {l2,l3};
    ((__nv_bfloat162*)(hi + idx))[0] = hh0;
    ((__nv_bfloat162*)(hi + idx))[1] = hh1;
    ((__nv_bfloat162*)(lo + idx))[0] = ll0;
    ((__nv_bfloat162*)(lo + idx))[1] = ll1;
}

// ---------------- cp.async helpers ----------------
__device__ __forceinline__ void cpa16(void* dst, const void* src) {
    unsigned s = (unsigned)__cvta_generic_to_shared(dst);
    asm volatile("cp.async.cg.shared.global [%0], [%1], 16;" :: "r"(s), "l"(src));
}
#define CP_COMMIT() asm volatile("cp.async.commit_group;")
#define CP_WAIT0()  asm volatile("cp.async.wait_group 0;" ::: "memory")

// ---------------- block reduce (sum, broadcast) ----------------
__device__ __forceinline__ float blockReduceSum(float v) {
    __shared__ float sh[32];
    int lane = threadIdx.x & 31;
    int wid  = threadIdx.x >> 5;
    int nw   = blockDim.x >> 5;
    #pragma unroll
    for (int o = 16; o; o >>= 1) v += __shfl_xor_sync(0xffffffffu, v, o);
    if (lane == 0) sh[wid] = v;
    __syncthreads();
    if (threadIdx.x == 0) {
        float s = 0.f;
        for (int i = 0; i < nw; i++) s += sh[i];
        sh[0] = s;
    }
    __syncthreads();
    float r = sh[0];
    __syncthreads();
    return r;
}

// ---------------- rope table ----------------
__global__ void rope_table_kernel(const int* __restrict__ pos_ids) {
    int s = blockIdx.x, i = threadIdx.x;
    float inv = exp2f(-(float)i * (13.287712379549449f / 64.0f));
    float ang = (float)pos_ids[s] * inv;
    float sn, cs;
    sincosf(ang, &sn, &cs);
    g_ropecos[s*64 + i] = cs;
    g_ropesin[s*64 + i] = sn;
}

// ---------------- RMSNorm over EMB=1024, writes hi/lo (+ optional fp32, + optional passthrough copy) ----
__global__ void rmsnorm_kernel(const float* __restrict__ x, const float* __restrict__ w,
                               bf16* __restrict__ ohi, bf16* __restrict__ olo,
                               float* __restrict__ ofp, float* __restrict__ ocopy) {
    int t = blockIdx.x;
    int d4 = threadIdx.x * 4;
    const float* xr = x + (long long)t * EMB;
    float4 v = *(const float4*)(xr + d4);
    long long idx = (long long)t * EMB + d4;
    if (ocopy) *(float4*)(ocopy + idx) = v;
    float ss = v.x*v.x + v.y*v.y + v.z*v.z + v.w*v.w;
    ss = blockReduceSum(ss);
    float scale = rsqrtf(ss * (1.0f / EMB) + EPSV);
    float4 wv = *(const float4*)(w + d4);
    float4 r;
    r.x = v.x*scale*wv.x; r.y = v.y*scale*wv.y;
    r.z = v.z*scale*wv.z; r.w = v.w*scale*wv.w;
    split_store4(r, ohi, olo, idx);
    if (ofp) *(float4*)(ofp + idx) = r;
}

// ---------------- per-head RMSNorm + RoPE: warp-per-head, shuffle-only ----------------
__global__ void qknorm_rope_kernel(const float* __restrict__ qkvbuf, const float* __restrict__ w,
                                   int colOff, bf16* __restrict__ ohi, bf16* __restrict__ olo,
                                   int outStride, float outScale, int H) {
    int gw = blockIdx.x * 4 + (threadIdx.x >> 5);
    int lane = threadIdx.x & 31;
    int t = gw / H, h = gw % H;
    const float* base = qkvbuf + (long long)t * QKVDIM + colOff + h * HEAD_DIM;
    float4 v = *(const float4*)(base + lane * 4);
    float ss = v.x*v.x + v.y*v.y + v.z*v.z + v.w*v.w;
    #pragma unroll
    for (int o = 16; o; o >>= 1) ss += __shfl_xor_sync(0xffffffffu, ss, o);
    float scale = rsqrtf(ss * (1.0f / HEAD_DIM) + EPSV);
    float4 wv = *(const float4*)(w + lane * 4);
    float4 nv;
    nv.x = v.x*scale*wv.x; nv.y = v.y*scale*wv.y;
    nv.z = v.z*scale*wv.z; nv.w = v.w*scale*wv.w;
    float ox = __shfl_xor_sync(0xffffffffu, nv.x, 16);
    float oy = __shfl_xor_sync(0xffffffffu, nv.y, 16);
    float oz = __shfl_xor_sync(0xffffffffu, nv.z, 16);
    float ow = __shfl_xor_sync(0xffffffffu, nv.w, 16);
    float sgn = (lane < 16) ? -1.f : 1.f;
    int s = t & (SEQ - 1);
    int i0 = (lane & 15) * 4;
    float4 cs = *(const float4*)(g_ropecos + s*64 + i0);
    float4 sn = *(const float4*)(g_ropesin + s*64 + i0);
    float4 r;
    r.x = (nv.x*cs.x + sgn*ox*sn.x) * outScale;
    r.y = (nv.y*cs.y + sgn*oy*sn.y) * outScale;
    r.z = (nv.z*cs.z + sgn*oz*sn.z) * outScale;
    r.w = (nv.w*cs.w + sgn*ow*sn.w) * outScale;
    split_store4(r, ohi, olo, (long long)t * outStride + h * HEAD_DIM + lane * 4);
}

// ---------------- V split from packed qkv ----------------
__global__ void vsplit_kernel() {
    int t = blockIdx.x;
    int d4 = threadIdx.x * 4;
    float4 v = *(const float4*)(g_qkv + (long long)t * QKVDIM + QDIM + KVDIM + d4);
    split_store4(v, g_vhi, g_vlo, (long long)t * KVDIM + d4);
}

// ---------------- bf16x3 GEMM (R10 core) with fused epilogues ----------------
// mode 0: normal (C [+res])
// mode 1: gate_up->SiLU fused: B cols permuted (gate/up interleaved per 128-block),
//         epilogue writes g_acthi/g_actlo directly (output stride MOE_HID).
// mode 2: down->combine fused: epilogue atomically adds w_slot * val into C[token].
#define GBM 128
#define GBN 128
#define GBK 32
#define BKP 40
#define GEMM_SMEM (8*GBM*BKP*2)   // 81920 B
#define STLD 132                  // epilogue stage ld (fp32)

__global__ __launch_bounds__(256, 2)
void gemm_tc(const bf16* __restrict__ Ahi, const bf16* __restrict__ Alo,
             const float* __restrict__ Bsrc,
             const float* __restrict__ Bsrc2, const float* __restrict__ Bsrc3,
             int nSplit1, int nSplit2,
             float* __restrict__ C, int Mtotal, int N, int K,
             const float* __restrict__ addres,
             const int* __restrict__ seg_off, const int* __restrict__ seg_cnt,
             const int* __restrict__ rowidx, long long strideB, int mode) {
    extern __shared__ char gsm[];
    bf16* sAhi = (bf16*)gsm;
    bf16* sAlo = sAhi + 2*GBM*BKP;
    bf16* sBhi = sAlo + 2*GBM*BKP;
    bf16* sBlo = sBhi + 2*GBN*BKP;

    int z = blockIdx.z;
    int mbase = 0, mcnt = Mtotal;
    if (seg_off) { mbase = seg_off[z]; mcnt = seg_cnt[z]; }
    int tm0 = blockIdx.y * GBM;
    if (tm0 >= mcnt) return;
    int tn0 = blockIdx.x * GBN;

    int tid = threadIdx.x;
    int wid = tid >> 5;
    int lane = tid & 31;
    int wm = wid & 3;
    int wn = wid >> 2;

    int lrow = tid >> 1;
    int lc0 = (tid & 1) * 16;

    int arowLocal = tm0 + lrow;
    bool avalid = (arowLocal < mcnt);
    long long arow = 0;
    if (avalid) arow = rowidx ? (long long)rowidx[mbase + arowLocal] : (long long)(mbase + arowLocal);
    const bf16* Ah = Ahi + arow * (long long)K + lc0;
    const bf16* Al = Alo + arow * (long long)K + lc0;

    // B row pointer: 3-way split (fused QKV) or gate/up permutation (mode 1)
    const float* Bload;
    {
        int n = tn0 + lrow;
        const float* base = Bsrc + (long long)z * strideB;
        long long nr = n;
        if (Bsrc2 && n >= nSplit1) {
            if (n < nSplit2) { base = Bsrc2; nr = n - nSplit1; }
            else             { base = Bsrc3; nr = n - nSplit2; }
        } else if (mode == 1) {
            int j = ((n >> 7) << 6) + (n & 63);
            nr = (n & 64) ? (MOE_HID + j) : j;
        }
        Bload = base + nr * (long long)K + lc0;
    }

    wmma::fragment<wmma::accumulator,16,16,16,float> acc[2][4];
    #pragma unroll
    for (int i = 0; i < 2; i++)
        #pragma unroll
        for (int j = 0; j < 4; j++) wmma::fill_fragment(acc[i][j], 0.f);

    int nIter = K / GBK;
    union Pack { bf16 b[8]; uint4 u; };
    int sOff = lrow*BKP + lc0;

    {
        cpa16(&sAhi[sOff],     Ah);
        cpa16(&sAhi[sOff + 8], Ah + 8);
        cpa16(&sAlo[sOff],     Al);
        cpa16(&sAlo[sOff + 8], Al + 8);
        CP_COMMIT();
        float4 b0 = *(const float4*)(Bload);
        float4 b1 = *(const float4*)(Bload+4);
        float4 b2 = *(const float4*)(Bload+8);
        float4 b3 = *(const float4*)(Bload+12);
        float bfv[16] = {b0.x,b0.y,b0.z,b0.w,b1.x,b1.y,b1.z,b1.w,
                         b2.x,b2.y,b2.z,b2.w,b3.x,b3.y,b3.z,b3.w};
        Pack Bh0, Bl0, Bh1, Bl1;
        #pragma unroll
        for (int e = 0; e < 8; e++) {
            split_bf16(bfv[e],   Bh0.b[e], Bl0.b[e]);
            split_bf16(bfv[e+8], Bh1.b[e], Bl1.b[e]);
        }
        *(uint4*)&sBhi[sOff]     = Bh0.u;
        *(uint4*)&sBhi[sOff + 8] = Bh1.u;
        *(uint4*)&sBlo[sOff]     = Bl0.u;
        *(uint4*)&sBlo[sOff + 8] = Bl1.u;
        CP_WAIT0();
    }
    __syncthreads();

    for (int it = 0; it < nIter; it++) {
        int cb = (it & 1) * GBM * BKP;
        int nb = ((it+1) & 1) * GBM * BKP;
        bool hasNext = (it + 1 < nIter);
        float4 b0, b1, b2, b3;
        if (hasNext) {
            int ko = (it+1)*GBK;
            cpa16(&sAhi[nb + sOff],     Ah + ko);
            cpa16(&sAhi[nb + sOff + 8], Ah + ko + 8);
            cpa16(&sAlo[nb + sOff],     Al + ko);
            cpa16(&sAlo[nb + sOff + 8], Al + ko + 8);
            CP_COMMIT();
            b0 = *(const float4*)(Bload + ko);
            b1 = *(const float4*)(Bload + ko + 4);
            b2 = *(const float4*)(Bload + ko + 8);
            b3 = *(const float4*)(Bload + ko + 12);
        }
        #pragma unroll
        for (int kk = 0; kk < GBK; kk += 16) {
            wmma::fragment<wmma::matrix_a,16,16,16,bf16,wmma::row_major> ahi[2], alo[2];
            #pragma unroll
            for (int i = 0; i < 2; i++) {
                wmma::load_matrix_sync(ahi[i], &sAhi[cb + (wm*32 + i*16)*BKP + kk], BKP);
                wmma::load_matrix_sync(alo[i], &sAlo[cb + (wm*32 + i*16)*BKP + kk], BKP);
            }
            #pragma unroll
            for (int jp = 0; jp < 2; jp++) {
                wmma::fragment<wmma::matrix_b,16,16,16,bf16,wmma::col_major> bhf[2], blf[2];
                #pragma unroll
                for (int jj = 0; jj < 2; jj++) {
                    int j = jp*2 + jj;
                    wmma::load_matrix_sync(bhf[jj], &sBhi[cb + (wn*64 + j*16)*BKP + kk], BKP);
                    wmma::load_matrix_sync(blf[jj], &sBlo[cb + (wn*64 + j*16)*BKP + kk], BKP);
                }
                #pragma unroll
                for (int jj = 0; jj < 2; jj++)
                    #pragma unroll
                    for (int i = 0; i < 2; i++)
                        wmma::mma_sync(acc[i][jp*2+jj], ahi[i], blf[jj], acc[i][jp*2+jj]);
                #pragma unroll
                for (int jj = 0; jj < 2; jj++)
                    #pragma unroll
                    for (int i = 0; i < 2; i++)
                        wmma::mma_sync(acc[i][jp*2+jj], alo[i], bhf[jj], acc[i][jp*2+jj]);
                #pragma unroll
                for (int jj = 0; jj < 2; jj++)
                    #pragma unroll
                    for (int i = 0; i < 2; i++)
                        wmma::mma_sync(acc[i][jp*2+jj], ahi[i], bhf[jj], acc[i][jp*2+jj]);
            }
        }
        if (hasNext) {
            float bfv[16] = {b0.x,b0.y,b0.z,b0.w,b1.x,b1.y,b1.z,b1.w,
                             b2.x,b2.y,b2.z,b2.w,b3.x,b3.y,b3.z,b3.w};
            Pack Bh0, Bl0, Bh1, Bl1;
            #pragma unroll
            for (int e = 0; e < 8; e++) {
                split_bf16(bfv[e],   Bh0.b[e], Bl0.b[e]);
                split_bf16(bfv[e+8], Bh1.b[e], Bl1.b[e]);
            }
            *(uint4*)&sBhi[nb + sOff]     = Bh0.u;
            *(uint4*)&sBhi[nb + sOff + 8] = Bh1.u;
            *(uint4*)&sBlo[nb + sOff]     = Bl0.u;
            *(uint4*)&sBlo[nb + sOff + 8] = Bl1.u;
            CP_WAIT0();
        }
        __syncthreads();
    }

    if (mode == 0) {
        bool full = (tm0 + GBM <= mcnt);
        if (full) {
            #pragma unroll
            for (int i = 0; i < 2; i++) {
                int grow = tm0 + wm*32 + i*16;
                #pragma unroll
                for (int j = 0; j < 4; j++) {
                    long long off = ((long long)(mbase + grow))*N + tn0 + wn*64 + j*16;
                    if (addres) {
                        wmma::fragment<wmma::accumulator,16,16,16,float> rf;
                        wmma::load_matrix_sync(rf, addres + off, N, wmma::mem_row_major);
                        #pragma unroll
                        for (int t = 0; t < rf.num_elements; t++) acc[i][j].x[t] += rf.x[t];
                    }
                    wmma::store_matrix_sync(C + off, acc[i][j], N, wmma::mem_row_major);
                }
            }
        } else {
            __syncthreads();
            float* stage = (float*)gsm + wid * 320;
            #pragma unroll
            for (int i = 0; i < 2; i++) {
                int growb = tm0 + wm*32 + i*16;
                #pragma unroll
                for (int j = 0; j < 4; j++) {
                    wmma::store_matrix_sync(stage, acc[i][j], 20, wmma::mem_row_major);
                    __syncwarp();
                    int gc0 = tn0 + wn*64 + j*16;
                    #pragma unroll
                    for (int e = 0; e < 8; e++) {
                        int idx = e*32 + lane;
                        int r = idx >> 4, c = idx & 15;
                        int grow = growb + r;
                        if (grow < mcnt) {
                            long long off = ((long long)(mbase + grow))*N + gc0 + c;
                            float vv = stage[r*20 + c];
                            if (addres) vv += addres[off];
                            C[off] = vv;
                        }
                    }
                    __syncwarp();
                }
            }
        }
    } else {
        // fused epilogues: stage full 128x128 tile in smem
        __syncthreads();
        float* stage = (float*)gsm;    // 128 x STLD fp32 = 67584 B < 81920
        #pragma unroll
        for (int i = 0; i < 2; i++)
            #pragma unroll
            for (int j = 0; j < 4; j++)
                wmma::store_matrix_sync(&stage[(wm*32 + i*16)*STLD + wn*64 + j*16],
                                        acc[i][j], STLD, wmma::mem_row_major);
        __syncthreads();
        if (mode == 1) {
            // silu(gate)*up -> acthi/lo ; block covers j in [blockIdx.x*64, +64)
            int j0 = blockIdx.x * 64;
            #pragma unroll
            for (int k = 0; k < 32; k++) {
                int lin = k*256 + tid;          // 0..8191 = 128 rows x 64 cols
                int r = lin >> 6, c = lin & 63;
                if (tm0 + r < mcnt) {
                    long long slot = mbase + tm0 + r;
                    float gt = stage[r*STLD + c];
                    float up = stage[r*STLD + 64 + c];
                    float a = gt / (1.f + __expf(-gt)) * up;
                    bf16 hh, ll;
                    split_bf16(a, hh, ll);
                    g_acthi[slot*MOE_HID + j0 + c] = hh;
                    g_actlo[slot*MOE_HID + j0 + c] = ll;
                }
            }
        } else {
            // weighted atomic combine into C[token]
            #pragma unroll
            for (int k = 0; k < 64; k++) {
                int lin = k*256 + tid;          // 0..16383 = 128 rows x 128 cols
                int r = lin >> 7, c = lin & 127;
                if (tm0 + r < mcnt) {
                    long long slot = mbase + tm0 + r;
                    int token = g_slot_token[slot];
                    float w = g_slot_w[slot];
                    atomicAdd(C + (long long)token*EMB + tn0 + c, w * stage[r*STLD + c]);
                }
            }
        }
    }
}

// ---------------- attention (R10): fixed-offset softmax, register ctx, cp.async KV ----------------
#define AQT 64
#define AKT 32
#define ALB 136
#define CLD 132
#define SLD 36
#define PLD 40
#define SMAX_OFF 12.0f
#define OF_QHI 0
#define OF_QLO (OF_QHI + AQT*ALB*2)
#define OF_KHI (OF_QLO + AQT*ALB*2)
#define OF_KLO (OF_KHI + 2*AKT*ALB*2)
#define OF_VHI (OF_KLO + 2*AKT*ALB*2)
#define OF_VLO (OF_VHI + 2*AKT*ALB*2)
#define OF_SC  (OF_VLO + 2*AKT*ALB*2)
#define OF_PHI (OF_SC  + AQT*SLD*4)
#define OF_PLO (OF_PHI + AQT*PLD*2)
#define OF_LS  (OF_PLO + AQT*PLD*2)
#define ATTN_SMEM (OF_LS + AQT*4)

__global__ __launch_bounds__(256)
void attn_tc() {
    extern __shared__ char asm_[];
    bf16* qhi = (bf16*)(asm_ + OF_QHI);
    bf16* qlo = (bf16*)(asm_ + OF_QLO);
    bf16* Khi = (bf16*)(asm_ + OF_KHI);
    bf16* Klo = (bf16*)(asm_ + OF_KLO);
    bf16* Vhi = (bf16*)(asm_ + OF_VHI);
    bf16* Vlo = (bf16*)(asm_ + OF_VLO);
    float* sc  = (float*)(asm_ + OF_SC);
    bf16* phi = (bf16*)(asm_ + OF_PHI);
    bf16* plo = (bf16*)(asm_ + OF_PLO);
    float* lsm = (float*)(asm_ + OF_LS);
    float* cts = (float*)(asm_ + OF_KHI);   // alias: used only after KV loop

    int q0 = SEQ - AQT - blockIdx.x * AQT;
    int h = blockIdx.y, b = blockIdx.z;
    int tid = threadIdx.x;
    int wid = tid >> 5;

    long long qoff = ((long long)b*SEQ + q0)*QDIM + (long long)h*HEAD_DIM;
    #pragma unroll
    for (int i = 0; i < 4; i++) {
        int lin = i*256 + tid;
        int r = lin >> 4, c = (lin & 15) * 8;
        *(uint4*)&qhi[r*ALB + c] = *(const uint4*)(g_qhi + qoff + (long long)r*QDIM + c);
        *(uint4*)&qlo[r*ALB + c] = *(const uint4*)(g_qlo + qoff + (long long)r*QDIM + c);
    }
    if (tid < AQT) lsm[tid] = 0.f;

    int kvh = h >> 2;
    long long kbase = (long long)b*SEQ*KVDIM + (long long)kvh*HEAD_DIM;

    int nT = q0 / AKT + 2;

    #pragma unroll
    for (int i = 0; i < 2; i++) {
        int lin = i*256 + tid;
        int r = lin >> 4, c = (lin & 15) * 8;
        long long goff = kbase + (long long)r*KVDIM + c;
        cpa16(&Khi[r*ALB + c], g_khi + goff);
        cpa16(&Klo[r*ALB + c], g_klo + goff);
        cpa16(&Vhi[r*ALB + c], g_vhi + goff);
        cpa16(&Vlo[r*ALB + c], g_vlo + goff);
    }
    CP_COMMIT();

    int mi = wid >> 1;
    int n0 = (wid & 1) * 64;
    wmma::fragment<wmma::accumulator,16,16,16,float> pacc[4];
    #pragma unroll
    for (int nj = 0; nj < 4; nj++) wmma::fill_fragment(pacc[nj], 0.f);

    int smr = (wid >> 1) * 16, snc = (wid & 1) * 16;

    for (int it = 0; it < nT; it++) {
        int t0 = it * AKT;
        int cb = (it & 1) * AKT * ALB;
        CP_WAIT0();
        __syncthreads();
        if (it + 1 < nT) {
            int nb = ((it+1) & 1) * AKT * ALB;
            int t1 = t0 + AKT;
            #pragma unroll
            for (int i = 0; i < 2; i++) {
                int lin = i*256 + tid;
                int r = lin >> 4, c = (lin & 15) * 8;
                long long goff = kbase + (long long)(t1+r)*KVDIM + c;
                cpa16(&Khi[nb + r*ALB + c], g_khi + goff);
                cpa16(&Klo[nb + r*ALB + c], g_klo + goff);
                cpa16(&Vhi[nb + r*ALB + c], g_vhi + goff);
                cpa16(&Vlo[nb + r*ALB + c], g_vlo + goff);
            }
            CP_COMMIT();
        }

        {
            wmma::fragment<wmma::accumulator,16,16,16,float> sacc0, sacc1;
            wmma::fill_fragment(sacc0, 0.f);
            wmma::fill_fragment(sacc1, 0.f);
            #pragma unroll
            for (int kk = 0; kk < HEAD_DIM; kk += 32) {
                wmma::fragment<wmma::matrix_a,16,16,16,bf16,wmma::row_major> a0h,a0l,a1h,a1l;
                wmma::fragment<wmma::matrix_b,16,16,16,bf16,wmma::col_major> b0h,b0l,b1h,b1l;
                wmma::load_matrix_sync(a0h, &qhi[smr*ALB + kk], ALB);
                wmma::load_matrix_sync(a0l, &qlo[smr*ALB + kk], ALB);
                wmma::load_matrix_sync(b0h, &Khi[cb + snc*ALB + kk], ALB);
                wmma::load_matrix_sync(b0l, &Klo[cb + snc*ALB + kk], ALB);
                wmma::load_matrix_sync(a1h, &qhi[smr*ALB + kk + 16], ALB);
                wmma::load_matrix_sync(a1l, &qlo[smr*ALB + kk + 16], ALB);
                wmma::load_matrix_sync(b1h, &Khi[cb + snc*ALB + kk + 16], ALB);
                wmma::load_matrix_sync(b1l, &Klo[cb + snc*ALB + kk + 16], ALB);
                wmma::mma_sync(sacc0, a0h, b0l, sacc0);
                wmma::mma_sync(sacc1, a1h, b1l, sacc1);
                wmma::mma_sync(sacc0, a0l, b0h, sacc0);
                wmma::mma_sync(sacc1, a1l, b1h, sacc1);
                wmma::mma_sync(sacc0, a0h, b0h, sacc0);
                wmma::mma_sync(sacc1, a1h, b1h, sacc1);
            }
            #pragma unroll
            for (int t = 0; t < sacc0.num_elements; t++) sacc0.x[t] += sacc1.x[t];
            wmma::store_matrix_sync(&sc[smr*SLD + snc], sacc0, SLD, wmma::mem_row_major);
        }
        __syncthreads();

        {
            int r = tid >> 2, sub = tid & 3;
            float sum = 0.f;
            #pragma unroll
            for (int cc = 0; cc < 8; cc++) {
                int c = sub*8 + cc;
                float p = (t0 + c <= q0 + r) ? __expf(sc[r*SLD + c] - SMAX_OFF) : 0.f;
                sum += p;
                bf16 ph, pl;
                split_bf16(p, ph, pl);
                phi[r*PLD + c] = ph;
                plo[r*PLD + c] = pl;
            }
            sum += __shfl_xor_sync(0xffffffffu, sum, 1);
            sum += __shfl_xor_sync(0xffffffffu, sum, 2);
            if (sub == 0) lsm[r] += sum;
        }
        __syncthreads();

        #pragma unroll
        for (int kk = 0; kk < AKT; kk += 16) {
            wmma::fragment<wmma::matrix_a,16,16,16,bf16,wmma::row_major> ahi, alo;
            wmma::load_matrix_sync(ahi, &phi[(mi*16)*PLD + kk], PLD);
            wmma::load_matrix_sync(alo, &plo[(mi*16)*PLD + kk], PLD);
            wmma::fragment<wmma::matrix_b,16,16,16,bf16,wmma::row_major> bhi[4], blo[4];
            #pragma unroll
            for (int nj = 0; nj < 4; nj++) {
                wmma::load_matrix_sync(bhi[nj], &Vhi[cb + kk*ALB + n0 + nj*16], ALB);
                wmma::load_matrix_sync(blo[nj], &Vlo[cb + kk*ALB + n0 + nj*16], ALB);
            }
            #pragma unroll
            for (int nj = 0; nj < 4; nj++)
                wmma::mma_sync(pacc[nj], ahi, blo[nj], pacc[nj]);
            #pragma unroll
            for (int nj = 0; nj < 4; nj++)
                wmma::mma_sync(pacc[nj], alo, bhi[nj], pacc[nj]);
            #pragma unroll
            for (int nj = 0; nj < 4; nj++)
                wmma::mma_sync(pacc[nj], ahi, bhi[nj], pacc[nj]);
        }
    }

    __syncthreads();
    #pragma unroll
    for (int nj = 0; nj < 4; nj++)
        wmma::store_matrix_sync(&cts[(mi*16)*CLD + n0 + nj*16], pacc[nj], CLD, wmma::mem_row_major);
    __syncthreads();

    #pragma unroll
    for (int i = 0; i < 8; i++) {
        int lin = i*256 + tid;
        int r = lin >> 5, c4 = (lin & 31) << 2;
        float inv = 1.f / lsm[r];
        float4 cv = *(float4*)&cts[r*CLD + c4];
        cv.x *= inv; cv.y *= inv; cv.z *= inv; cv.w *= inv;
        split_store4(cv, g_ctxhi, g_ctxlo, qoff + (long long)r*QDIM + c4);
    }
}

// ---------------- MoE routing ----------------
__global__ void reset_kernel() {
    if (threadIdx.x < N_EXP) g_counts[threadIdx.x] = 0;
}

__global__ void router_kernel(const float* __restrict__ h, const float* __restrict__ rw) {
    int warp = threadIdx.x >> 5, lane = threadIdx.x & 31;
    int t = blockIdx.x * 4 + warp;
    const float* hr = h + (long long)t * EMB;
    float lg[N_EXP];
    #pragma unroll
    for (int e = 0; e < N_EXP; e++) {
        float p = 0.f;
        for (int d = lane; d < EMB; d += 32) p += hr[d] * rw[e * EMB + d];
        #pragma unroll
        for (int o = 16; o; o >>= 1) p += __shfl_xor_sync(0xffffffffu, p, o);
        lg[e] = __shfl_sync(0xffffffffu, p, 0);
    }
    if (lane == 0) {
        int i1 = 0;
        #pragma unroll
        for (int e = 1; e < N_EXP; e++) if (lg[e] > lg[i1]) i1 = e;
        int i2 = -1;
        #pragma unroll
        for (int e = 0; e < N_EXP; e++) {
            if (e == i1) continue;
            if (i2 < 0 || lg[e] > lg[i2]) i2 = e;
        }
        float e1 = expf(lg[i2] - lg[i1]);
        float w0 = 1.f / (1.f + e1);
        float w1 = e1 / (1.f + e1);
        g_topk_idx[t*2]   = i1;  g_topk_idx[t*2+1] = i2;
        g_topk_w[t*2]     = w0;  g_topk_w[t*2+1]   = w1;
        atomicAdd(&g_counts[i1], 1);
        atomicAdd(&g_counts[i2], 1);
    }
}

__global__ void offsets_kernel() {
    if (threadIdx.x == 0) {
        int o = 0;
        for (int e = 0; e < N_EXP; e++) {
            g_off[e] = o; g_cursor[e] = o;
            o += g_counts[e];
        }
    }
}

__global__ void scatter_kernel() {
    int id = blockIdx.x * blockDim.x + threadIdx.x;
    if (id >= N_SLOT) return;
    int t = id >> 1;
    int e = g_topk_idx[id];
    int pos = atomicAdd(&g_cursor[e], 1);
    g_slot_token[pos] = t;
    g_slot_w[pos] = g_topk_w[id];
}

// ---------------- launch ----------------
extern "C" void kernel_launch(void* const* d_in, const int* in_sizes, int n_in,
                              void* d_out, int out_size) {
    const float* x        = (const float*)d_in[0];
    const int*   pos_ids  = (const int*)d_in[1];
    const float* norm1_w  = (const float*)d_in[3];
    const float* norm2_w  = (const float*)d_in[4];
    const float* qn_w     = (const float*)d_in[5];
    const float* kn_w     = (const float*)d_in[6];
    const float* q_w      = (const float*)d_in[7];
    const float* k_w      = (const float*)d_in[8];
    const float* v_w      = (const float*)d_in[9];
    const float* o_w      = (const float*)d_in[10];
    const float* router_w = (const float*)d_in[11];
    const float* gate_up  = (const float*)d_in[12];
    const float* down     = (const float*)d_in[13];
    float* out = (float*)d_out;

    bf16 *p_h1hi, *p_h1lo, *p_ctxhi, *p_ctxlo, *p_h2hi, *p_h2lo, *p_acthi, *p_actlo;
    bf16 *p_qhi, *p_qlo, *p_khi, *p_klo;
    float *p_qkv, *p_x1, *p_h2;
    int *p_off, *p_cnt, *p_slot_token;
    cudaGetSymbolAddress((void**)&p_h1hi, g_h1hi);
    cudaGetSymbolAddress((void**)&p_h1lo, g_h1lo);
    cudaGetSymbolAddress((void**)&p_qkv, g_qkv);
    cudaGetSymbolAddress((void**)&p_qhi, g_qhi);
    cudaGetSymbolAddress((void**)&p_qlo, g_qlo);
    cudaGetSymbolAddress((void**)&p_khi, g_khi);
    cudaGetSymbolAddress((void**)&p_klo, g_klo);
    cudaGetSymbolAddress((void**)&p_ctxhi, g_ctxhi);
    cudaGetSymbolAddress((void**)&p_ctxlo, g_ctxlo);
    cudaGetSymbolAddress((void**)&p_x1, g_x1);
    cudaGetSymbolAddress((void**)&p_h2, g_h2);
    cudaGetSymbolAddress((void**)&p_h2hi, g_h2hi);
    cudaGetSymbolAddress((void**)&p_h2lo, g_h2lo);
    cudaGetSymbolAddress((void**)&p_acthi, g_acthi);
    cudaGetSymbolAddress((void**)&p_actlo, g_actlo);
    cudaGetSymbolAddress((void**)&p_off, g_off);
    cudaGetSymbolAddress((void**)&p_cnt, g_counts);
    cudaGetSymbolAddress((void**)&p_slot_token, g_slot_token);

    static int smem_set = 0;
    if (!smem_set) {
        cudaFuncSetAttribute(attn_tc, cudaFuncAttributeMaxDynamicSharedMemorySize, ATTN_SMEM);
        cudaFuncSetAttribute(gemm_tc, cudaFuncAttributeMaxDynamicSharedMemorySize, GEMM_SMEM);
        smem_set = 1;
    }

    // 0) rope table
    rope_table_kernel<<<SEQ, 64>>>(pos_ids);

    // 1) pre-attention norm -> h1 hi/lo
    rmsnorm_kernel<<<T_TOK, 256>>>(x, norm1_w, p_h1hi, p_h1lo, nullptr, nullptr);

    // 2) fused QKV projection (3-way B source)
    gemm_tc<<<dim3(QKVDIM/GBN, T_TOK/GBM, 1), 256, GEMM_SMEM>>>(
        p_h1hi, p_h1lo, q_w, k_w, v_w, QDIM, QDIM + KVDIM,
        p_qkv, T_TOK, QKVDIM, EMB,
        nullptr, nullptr, nullptr, nullptr, 0, 0);

    // 3) per-head RMSNorm + RoPE (warp-per-head) + V split
    qknorm_rope_kernel<<<T_TOK*N_HEADS/4, 128>>>(
        p_qkv, qn_w, 0, p_qhi, p_qlo, QDIM, 0.08838834764831845f, N_HEADS);
    qknorm_rope_kernel<<<T_TOK*N_KV/4, 128>>>(
        p_qkv, kn_w, QDIM, p_khi, p_klo, KVDIM, 1.0f, N_KV);
    vsplit_kernel<<<T_TOK, 128>>>();

    // 4) causal GQA flash attention -> ctx hi/lo
    attn_tc<<<dim3(SEQ/AQT, N_HEADS, BATCH), 256, ATTN_SMEM>>>();

    // 5) output projection + residual
    gemm_tc<<<dim3(EMB/GBN, T_TOK/GBM, 1), 256, GEMM_SMEM>>>(
        p_ctxhi, p_ctxlo, o_w, nullptr, nullptr, 0, 0,
        p_x1, T_TOK, EMB, QDIM,
        x, nullptr, nullptr, nullptr, 0, 0);

    // 6) pre-MoE norm -> h2 fp32 (router) + hi/lo (gemm) + copy x1 into out (combine base)
    rmsnorm_kernel<<<T_TOK, 256>>>(p_x1, norm2_w, p_h2hi, p_h2lo, p_h2, out);

    // 7) routing (top-2) + expert grouping
    reset_kernel<<<1, 32>>>();
    router_kernel<<<T_TOK/4, 128>>>(p_h2, router_w);
    offsets_kernel<<<1, 32>>>();
    scatter_kernel<<<(N_SLOT + 255)/256, 256>>>();

    // 8) expert gate_up GEMM with fused SiLU -> act hi/lo (mode 1; permuted cols)
    gemm_tc<<<dim3((2*MOE_HID)/GBN, N_SLOT/GBM, N_EXP), 256, GEMM_SMEM>>>(
        p_h2hi, p_h2lo, gate_up, nullptr, nullptr, 0, 0,
        nullptr, N_SLOT, 2*MOE_HID, EMB,
        nullptr, p_off, p_cnt, p_slot_token, (long long)(2*MOE_HID)*EMB, 1);

    // 9) expert down GEMM with fused weighted combine into out (mode 2)
    gemm_tc<<<dim3(EMB/GBN, N_SLOT/GBM, N_EXP), 256, GEMM_SMEM>>>(
        p_acthi, p_actlo, down, nullptr, nullptr, 0, 0,
        out, N_SLOT, EMB, MOE_HID,
        nullptr, p_off, p_cnt, nullptr, (long long)EMB*MOE_HID, 2);

    (void)in_sizes; (void)n_in; (void)out_size;
}

// round 15
// speedup vs baseline: 1.0045x; 1.0045x over previous
#include <cuda_runtime.h>
#include <cuda_bf16.h>
#include <mma.h>
#include <math.h>

using namespace nvcuda;

// ---------------- problem constants ----------------
#define EMB      1024
#define N_HEADS  16
#define N_KV     4
#define HEAD_DIM 128
#define N_EXP    8
#define TOP_K    2
#define MOE_HID  1024
#define BATCH    2
#define SEQ      2048
#define T_TOK    (BATCH*SEQ)          // 4096
#define QDIM     (N_HEADS*HEAD_DIM)   // 2048
#define KVDIM    (N_KV*HEAD_DIM)      // 512
#define QKVDIM   (QDIM + 2*KVDIM)     // 3072
#define N_SLOT   (T_TOK*TOP_K)        // 8192
#define EPSV     1e-6f

typedef __nv_bfloat16 bf16;

// ---------------- scratch (device globals; no allocation allowed) ----------------
__device__ bf16  g_h1hi[T_TOK*EMB],  g_h1lo[T_TOK*EMB];
__device__ float g_qkv[T_TOK*QKVDIM];
__device__ bf16  g_qhi[T_TOK*QDIM],  g_qlo[T_TOK*QDIM];
__device__ bf16  g_khi[T_TOK*KVDIM], g_klo[T_TOK*KVDIM];
__device__ bf16  g_vhi[T_TOK*KVDIM], g_vlo[T_TOK*KVDIM];
__device__ bf16  g_ctxhi[T_TOK*QDIM], g_ctxlo[T_TOK*QDIM];
__device__ float g_x1[T_TOK*EMB];
__device__ float g_h2[T_TOK*EMB];
__device__ bf16  g_h2hi[T_TOK*EMB],  g_h2lo[T_TOK*EMB];
__device__ bf16  g_acthi[N_SLOT*MOE_HID], g_actlo[N_SLOT*MOE_HID];
__device__ float g_outslot[N_SLOT*EMB];
__device__ float g_ropecos[SEQ*64], g_ropesin[SEQ*64];
__device__ int   g_topk_idx[N_SLOT];
__device__ float g_topk_w[N_SLOT];
__device__ int   g_counts[N_EXP];
__device__ int   g_off[N_EXP];
__device__ int   g_cursor[N_EXP];
__device__ int   g_slot_token[N_SLOT];
__device__ int   g_slot_of[N_SLOT];

// ---------------- bf16 hi/lo split helpers ----------------
__device__ __forceinline__ void split_bf16(float x, bf16& hi, bf16& lo) {
    hi = __float2bfloat16(x);
    lo = __float2bfloat16(x - __bfloat162float(hi));
}
__device__ __forceinline__ void split_store4(float4 v, bf16* hi, bf16* lo, long long idx) {
    bf16 h0,l0,h1,l1,h2,l2,h3,l3;
    split_bf16(v.x,h0,l0); split_bf16(v.y,h1,l1);
    split_bf16(v.z,h2,l2); split_bf16(v.w,h3,l3);
    __nv_bfloat162 hh0 = {h0,h1}, hh1 = {h2,h3};
    __nv_bfloat162 ll0 = {l0,l1}, ll1 = {l2,l3};
    ((__nv_bfloat162*)(hi + idx))[0] = hh0;
    ((__nv_bfloat162*)(hi + idx))[1] = hh1;
    ((__nv_bfloat162*)(lo + idx))[0] = ll0;
    ((__nv_bfloat162*)(lo + idx))[1] = ll1;
}

// ---------------- cp.async helpers ----------------
__device__ __forceinline__ void cpa16(void* dst, const void* src) {
    unsigned s = (unsigned)__cvta_generic_to_shared(dst);
    asm volatile("cp.async.cg.shared.global [%0], [%1], 16;" :: "r"(s), "l"(src));
}
#define CP_COMMIT() asm volatile("cp.async.commit_group;")
#define CP_WAIT0()  asm volatile("cp.async.wait_group 0;" ::: "memory")

// ---------------- block reduce (sum, broadcast) ----------------
__device__ __forceinline__ float blockReduceSum(float v) {
    __shared__ float sh[32];
    int lane = threadIdx.x & 31;
    int wid  = threadIdx.x >> 5;
    int nw   = blockDim.x >> 5;
    #pragma unroll
    for (int o = 16; o; o >>= 1) v += __shfl_xor_sync(0xffffffffu, v, o);
    if (lane == 0) sh[wid] = v;
    __syncthreads();
    if (threadIdx.x == 0) {
        float s = 0.f;
        for (int i = 0; i < nw; i++) s += sh[i];
        sh[0] = s;
    }
    __syncthreads();
    float r = sh[0];
    __syncthreads();
    return r;
}

// ---------------- rope table ----------------
__global__ void rope_table_kernel(const int* __restrict__ pos_ids) {
    int s = blockIdx.x, i = threadIdx.x;
    float inv = exp2f(-(float)i * (13.287712379549449f / 64.0f));
    float ang = (float)pos_ids[s] * inv;
    float sn, cs;
    sincosf(ang, &sn, &cs);
    g_ropecos[s*64 + i] = cs;
    g_ropesin[s*64 + i] = sn;
}

// ---------------- RMSNorm over EMB=1024, writes hi/lo (+ optional fp32) ----------------
__global__ void rmsnorm_kernel(const float* __restrict__ x, const float* __restrict__ w,
                               bf16* __restrict__ ohi, bf16* __restrict__ olo,
                               float* __restrict__ ofp) {
    int t = blockIdx.x;
    int d4 = threadIdx.x * 4;
    const float* xr = x + (long long)t * EMB;
    float4 v = *(const float4*)(xr + d4);
    long long idx = (long long)t * EMB + d4;
    float ss = v.x*v.x + v.y*v.y + v.z*v.z + v.w*v.w;
    ss = blockReduceSum(ss);
    float scale = rsqrtf(ss * (1.0f / EMB) + EPSV);
    float4 wv = *(const float4*)(w + d4);
    float4 r;
    r.x = v.x*scale*wv.x; r.y = v.y*scale*wv.y;
    r.z = v.z*scale*wv.z; r.w = v.w*scale*wv.w;
    split_store4(r, ohi, olo, idx);
    if (ofp) *(float4*)(ofp + idx) = r;
}

// ---------------- per-head RMSNorm + RoPE: warp-per-head, shuffle-only ----------------
__global__ void qknorm_rope_kernel(const float* __restrict__ qkvbuf, const float* __restrict__ w,
                                   int colOff, bf16* __restrict__ ohi, bf16* __restrict__ olo,
                                   int outStride, float outScale, int H) {
    int gw = blockIdx.x * 4 + (threadIdx.x >> 5);
    int lane = threadIdx.x & 31;
    int t = gw / H, h = gw % H;
    const float* base = qkvbuf + (long long)t * QKVDIM + colOff + h * HEAD_DIM;
    float4 v = *(const float4*)(base + lane * 4);
    float ss = v.x*v.x + v.y*v.y + v.z*v.z + v.w*v.w;
    #pragma unroll
    for (int o = 16; o; o >>= 1) ss += __shfl_xor_sync(0xffffffffu, ss, o);
    float scale = rsqrtf(ss * (1.0f / HEAD_DIM) + EPSV);
    float4 wv = *(const float4*)(w + lane * 4);
    float4 nv;
    nv.x = v.x*scale*wv.x; nv.y = v.y*scale*wv.y;
    nv.z = v.z*scale*wv.z; nv.w = v.w*scale*wv.w;
    float ox = __shfl_xor_sync(0xffffffffu, nv.x, 16);
    float oy = __shfl_xor_sync(0xffffffffu, nv.y, 16);
    float oz = __shfl_xor_sync(0xffffffffu, nv.z, 16);
    float ow = __shfl_xor_sync(0xffffffffu, nv.w, 16);
    float sgn = (lane < 16) ? -1.f : 1.f;
    int s = t & (SEQ - 1);
    int i0 = (lane & 15) * 4;
    float4 cs = *(const float4*)(g_ropecos + s*64 + i0);
    float4 sn = *(const float4*)(g_ropesin + s*64 + i0);
    float4 r;
    r.x = (nv.x*cs.x + sgn*ox*sn.x) * outScale;
    r.y = (nv.y*cs.y + sgn*oy*sn.y) * outScale;
    r.z = (nv.z*cs.z + sgn*oz*sn.z) * outScale;
    r.w = (nv.w*cs.w + sgn*ow*sn.w) * outScale;
    split_store4(r, ohi, olo, (long long)t * outStride + h * HEAD_DIM + lane * 4);
}

// ---------------- V split from packed qkv ----------------
__global__ void vsplit_kernel() {
    int t = blockIdx.x;
    int d4 = threadIdx.x * 4;
    float4 v = *(const float4*)(g_qkv + (long long)t * QKVDIM + QDIM + KVDIM + d4);
    split_store4(v, g_vhi, g_vlo, (long long)t * KVDIM + d4);
}

// ---------------- bf16x3 GEMM (R10 core) with optional fused SiLU epilogue ----------------
// mode 0: normal (C [+res])
// mode 1: gate_up->SiLU fused: B cols permuted (gate/up interleaved per 128-block),
//         epilogue writes g_acthi/g_actlo directly (output stride MOE_HID).
#define GBM 128
#define GBN 128
#define GBK 32
#define BKP 40
#define GEMM_SMEM (8*GBM*BKP*2)   // 81920 B
#define STLD 132                  // epilogue stage ld (fp32)

__global__ __launch_bounds__(256, 2)
void gemm_tc(const bf16* __restrict__ Ahi, const bf16* __restrict__ Alo,
             const float* __restrict__ Bsrc,
             const float* __restrict__ Bsrc2, const float* __restrict__ Bsrc3,
             int nSplit1, int nSplit2,
             float* __restrict__ C, int Mtotal, int N, int K,
             const float* __restrict__ addres,
             const int* __restrict__ seg_off, const int* __restrict__ seg_cnt,
             const int* __restrict__ rowidx, long long strideB, int mode) {
    extern __shared__ char gsm[];
    bf16* sAhi = (bf16*)gsm;
    bf16* sAlo = sAhi + 2*GBM*BKP;
    bf16* sBhi = sAlo + 2*GBM*BKP;
    bf16* sBlo = sBhi + 2*GBN*BKP;

    int z = blockIdx.z;
    int mbase = 0, mcnt = Mtotal;
    if (seg_off) { mbase = seg_off[z]; mcnt = seg_cnt[z]; }
    int tm0 = blockIdx.y * GBM;
    if (tm0 >= mcnt) return;
    int tn0 = blockIdx.x * GBN;

    int tid = threadIdx.x;
    int wid = tid >> 5;
    int lane = tid & 31;
    int wm = wid & 3;
    int wn = wid >> 2;

    int lrow = tid >> 1;
    int lc0 = (tid & 1) * 16;

    int arowLocal = tm0 + lrow;
    bool avalid = (arowLocal < mcnt);
    long long arow = 0;
    if (avalid) arow = rowidx ? (long long)rowidx[mbase + arowLocal] : (long long)(mbase + arowLocal);
    const bf16* Ah = Ahi + arow * (long long)K + lc0;
    const bf16* Al = Alo + arow * (long long)K + lc0;

    // B row pointer: 3-way split (fused QKV) or gate/up permutation (mode 1)
    const float* Bload;
    {
        int n = tn0 + lrow;
        const float* base = Bsrc + (long long)z * strideB;
        long long nr = n;
        if (Bsrc2 && n >= nSplit1) {
            if (n < nSplit2) { base = Bsrc2; nr = n - nSplit1; }
            else             { base = Bsrc3; nr = n - nSplit2; }
        } else if (mode == 1) {
            int j = ((n >> 7) << 6) + (n & 63);
            nr = (n & 64) ? (MOE_HID + j) : j;
        }
        Bload = base + nr * (long long)K + lc0;
    }

    wmma::fragment<wmma::accumulator,16,16,16,float> acc[2][4];
    #pragma unroll
    for (int i = 0; i < 2; i++)
        #pragma unroll
        for (int j = 0; j < 4; j++) wmma::fill_fragment(acc[i][j], 0.f);

    int nIter = K / GBK;
    union Pack { bf16 b[8]; uint4 u; };
    int sOff = lrow*BKP + lc0;

    {
        cpa16(&sAhi[sOff],     Ah);
        cpa16(&sAhi[sOff + 8], Ah + 8);
        cpa16(&sAlo[sOff],     Al);
        cpa16(&sAlo[sOff + 8], Al + 8);
        CP_COMMIT();
        float4 b0 = *(const float4*)(Bload);
        float4 b1 = *(const float4*)(Bload+4);
        float4 b2 = *(const float4*)(Bload+8);
        float4 b3 = *(const float4*)(Bload+12);
        float bfv[16] = {b0.x,b0.y,b0.z,b0.w,b1.x,b1.y,b1.z,b1.w,
                         b2.x,b2.y,b2.z,b2.w,b3.x,b3.y,b3.z,b3.w};
        Pack Bh0, Bl0, Bh1, Bl1;
        #pragma unroll
        for (int e = 0; e < 8; e++) {
            split_bf16(bfv[e],   Bh0.b[e], Bl0.b[e]);
            split_bf16(bfv[e+8], Bh1.b[e], Bl1.b[e]);
        }
        *(uint4*)&sBhi[sOff]     = Bh0.u;
        *(uint4*)&sBhi[sOff + 8] = Bh1.u;
        *(uint4*)&sBlo[sOff]     = Bl0.u;
        *(uint4*)&sBlo[sOff + 8] = Bl1.u;
        CP_WAIT0();
    }
    __syncthreads();

    for (int it = 0; it < nIter; it++) {
        int cb = (it & 1) * GBM * BKP;
        int nb = ((it+1) & 1) * GBM * BKP;
        bool hasNext = (it + 1 < nIter);
        float4 b0, b1, b2, b3;
        if (hasNext) {
            int ko = (it+1)*GBK;
            cpa16(&sAhi[nb + sOff],     Ah + ko);
            cpa16(&sAhi[nb + sOff + 8], Ah + ko + 8);
            cpa16(&sAlo[nb + sOff],     Al + ko);
            cpa16(&sAlo[nb + sOff + 8], Al + ko + 8);
            CP_COMMIT();
            b0 = *(const float4*)(Bload + ko);
            b1 = *(const float4*)(Bload + ko + 4);
            b2 = *(const float4*)(Bload + ko + 8);
            b3 = *(const float4*)(Bload + ko + 12);
        }
        #pragma unroll
        for (int kk = 0; kk < GBK; kk += 16) {
            wmma::fragment<wmma::matrix_a,16,16,16,bf16,wmma::row_major> ahi[2], alo[2];
            #pragma unroll
            for (int i = 0; i < 2; i++) {
                wmma::load_matrix_sync(ahi[i], &sAhi[cb + (wm*32 + i*16)*BKP + kk], BKP);
                wmma::load_matrix_sync(alo[i], &sAlo[cb + (wm*32 + i*16)*BKP + kk], BKP);
            }
            #pragma unroll
            for (int jp = 0; jp < 2; jp++) {
                wmma::fragment<wmma::matrix_b,16,16,16,bf16,wmma::col_major> bhf[2], blf[2];
                #pragma unroll
                for (int jj = 0; jj < 2; jj++) {
                    int j = jp*2 + jj;
                    wmma::load_matrix_sync(bhf[jj], &sBhi[cb + (wn*64 + j*16)*BKP + kk], BKP);
                    wmma::load_matrix_sync(blf[jj], &sBlo[cb + (wn*64 + j*16)*BKP + kk], BKP);
                }
                #pragma unroll
                for (int jj = 0; jj < 2; jj++)
                    #pragma unroll
                    for (int i = 0; i < 2; i++)
                        wmma::mma_sync(acc[i][jp*2+jj], ahi[i], blf[jj], acc[i][jp*2+jj]);
                #pragma unroll
                for (int jj = 0; jj < 2; jj++)
                    #pragma unroll
                    for (int i = 0; i < 2; i++)
                        wmma::mma_sync(acc[i][jp*2+jj], alo[i], bhf[jj], acc[i][jp*2+jj]);
                #pragma unroll
                for (int jj = 0; jj < 2; jj++)
                    #pragma unroll
                    for (int i = 0; i < 2; i++)
                        wmma::mma_sync(acc[i][jp*2+jj], ahi[i], bhf[jj], acc[i][jp*2+jj]);
            }
        }
        if (hasNext) {
            float bfv[16] = {b0.x,b0.y,b0.z,b0.w,b1.x,b1.y,b1.z,b1.w,
                             b2.x,b2.y,b2.z,b2.w,b3.x,b3.y,b3.z,b3.w};
            Pack Bh0, Bl0, Bh1, Bl1;
            #pragma unroll
            for (int e = 0; e < 8; e++) {
                split_bf16(bfv[e],   Bh0.b[e], Bl0.b[e]);
                split_bf16(bfv[e+8], Bh1.b[e], Bl1.b[e]);
            }
            *(uint4*)&sBhi[nb + sOff]     = Bh0.u;
            *(uint4*)&sBhi[nb + sOff + 8] = Bh1.u;
            *(uint4*)&sBlo[nb + sOff]     = Bl0.u;
            *(uint4*)&sBlo[nb + sOff + 8] = Bl1.u;
            CP_WAIT0();
        }
        __syncthreads();
    }

    if (mode == 0) {
        bool full = (tm0 + GBM <= mcnt);
        if (full) {
            #pragma unroll
            for (int i = 0; i < 2; i++) {
                int grow = tm0 + wm*32 + i*16;
                #pragma unroll
                for (int j = 0; j < 4; j++) {
                    long long off = ((long long)(mbase + grow))*N + tn0 + wn*64 + j*16;
                    if (addres) {
                        wmma::fragment<wmma::accumulator,16,16,16,float> rf;
                        wmma::load_matrix_sync(rf, addres + off, N, wmma::mem_row_major);
                        #pragma unroll
                        for (int t = 0; t < rf.num_elements; t++) acc[i][j].x[t] += rf.x[t];
                    }
                    wmma::store_matrix_sync(C + off, acc[i][j], N, wmma::mem_row_major);
                }
            }
        } else {
            __syncthreads();
            float* stage = (float*)gsm + wid * 320;
            #pragma unroll
            for (int i = 0; i < 2; i++) {
                int growb = tm0 + wm*32 + i*16;
                #pragma unroll
                for (int j = 0; j < 4; j++) {
                    wmma::store_matrix_sync(stage, acc[i][j], 20, wmma::mem_row_major);
                    __syncwarp();
                    int gc0 = tn0 + wn*64 + j*16;
                    #pragma unroll
                    for (int e = 0; e < 8; e++) {
                        int idx = e*32 + lane;
                        int r = idx >> 4, c = idx & 15;
                        int grow = growb + r;
                        if (grow < mcnt) {
                            long long off = ((long long)(mbase + grow))*N + gc0 + c;
                            float vv = stage[r*20 + c];
                            if (addres) vv += addres[off];
                            C[off] = vv;
                        }
                    }
                    __syncwarp();
                }
            }
        }
    } else {
        // fused SiLU epilogue: stage full 128x128 tile in smem
        __syncthreads();
        float* stage = (float*)gsm;    // 128 x STLD fp32 = 67584 B < 81920
        #pragma unroll
        for (int i = 0; i < 2; i++)
            #pragma unroll
            for (int j = 0; j < 4; j++)
                wmma::store_matrix_sync(&stage[(wm*32 + i*16)*STLD + wn*64 + j*16],
                                        acc[i][j], STLD, wmma::mem_row_major);
        __syncthreads();
        int j0 = blockIdx.x * 64;
        #pragma unroll
        for (int k = 0; k < 32; k++) {
            int lin = k*256 + tid;          // 0..8191 = 128 rows x 64 cols
            int r = lin >> 6, c = lin & 63;
            if (tm0 + r < mcnt) {
                long long slot = mbase + tm0 + r;
                float gt = stage[r*STLD + c];
                float up = stage[r*STLD + 64 + c];
                float a = gt / (1.f + __expf(-gt)) * up;
                bf16 hh, ll;
                split_bf16(a, hh, ll);
                g_acthi[slot*MOE_HID + j0 + c] = hh;
                g_actlo[slot*MOE_HID + j0 + c] = ll;
            }
        }
    }
}

// ---------------- attention (R10): fixed-offset softmax, register ctx, cp.async KV ----------------
#define AQT 64
#define AKT 32
#define ALB 136
#define CLD 132
#define SLD 36
#define PLD 40
#define SMAX_OFF 12.0f
#define OF_QHI 0
#define OF_QLO (OF_QHI + AQT*ALB*2)
#define OF_KHI (OF_QLO + AQT*ALB*2)
#define OF_KLO (OF_KHI + 2*AKT*ALB*2)
#define OF_VHI (OF_KLO + 2*AKT*ALB*2)
#define OF_VLO (OF_VHI + 2*AKT*ALB*2)
#define OF_SC  (OF_VLO + 2*AKT*ALB*2)
#define OF_PHI (OF_SC  + AQT*SLD*4)
#define OF_PLO (OF_PHI + AQT*PLD*2)
#define OF_LS  (OF_PLO + AQT*PLD*2)
#define ATTN_SMEM (OF_LS + AQT*4)

__global__ __launch_bounds__(256)
void attn_tc() {
    extern __shared__ char asm_[];
    bf16* qhi = (bf16*)(asm_ + OF_QHI);
    bf16* qlo = (bf16*)(asm_ + OF_QLO);
    bf16* Khi = (bf16*)(asm_ + OF_KHI);
    bf16* Klo = (bf16*)(asm_ + OF_KLO);
    bf16* Vhi = (bf16*)(asm_ + OF_VHI);
    bf16* Vlo = (bf16*)(asm_ + OF_VLO);
    float* sc  = (float*)(asm_ + OF_SC);
    bf16* phi = (bf16*)(asm_ + OF_PHI);
    bf16* plo = (bf16*)(asm_ + OF_PLO);
    float* lsm = (float*)(asm_ + OF_LS);
    float* cts = (float*)(asm_ + OF_KHI);   // alias: used only after KV loop

    int q0 = SEQ - AQT - blockIdx.x * AQT;
    int h = blockIdx.y, b = blockIdx.z;
    int tid = threadIdx.x;
    int wid = tid >> 5;

    long long qoff = ((long long)b*SEQ + q0)*QDIM + (long long)h*HEAD_DIM;
    #pragma unroll
    for (int i = 0; i < 4; i++) {
        int lin = i*256 + tid;
        int r = lin >> 4, c = (lin & 15) * 8;
        *(uint4*)&qhi[r*ALB + c] = *(const uint4*)(g_qhi + qoff + (long long)r*QDIM + c);
        *(uint4*)&qlo[r*ALB + c] = *(const uint4*)(g_qlo + qoff + (long long)r*QDIM + c);
    }
    if (tid < AQT) lsm[tid] = 0.f;

    int kvh = h >> 2;
    long long kbase = (long long)b*SEQ*KVDIM + (long long)kvh*HEAD_DIM;

    int nT = q0 / AKT + 2;

    #pragma unroll
    for (int i = 0; i < 2; i++) {
        int lin = i*256 + tid;
        int r = lin >> 4, c = (lin & 15) * 8;
        long long goff = kbase + (long long)r*KVDIM + c;
        cpa16(&Khi[r*ALB + c], g_khi + goff);
        cpa16(&Klo[r*ALB + c], g_klo + goff);
        cpa16(&Vhi[r*ALB + c], g_vhi + goff);
        cpa16(&Vlo[r*ALB + c], g_vlo + goff);
    }
    CP_COMMIT();

    int mi = wid >> 1;
    int n0 = (wid & 1) * 64;
    wmma::fragment<wmma::accumulator,16,16,16,float> pacc[4];
    #pragma unroll
    for (int nj = 0; nj < 4; nj++) wmma::fill_fragment(pacc[nj], 0.f);

    int smr = (wid >> 1) * 16, snc = (wid & 1) * 16;

    for (int it = 0; it < nT; it++) {
        int t0 = it * AKT;
        int cb = (it & 1) * AKT * ALB;
        CP_WAIT0();
        __syncthreads();
        if (it + 1 < nT) {
            int nb = ((it+1) & 1) * AKT * ALB;
            int t1 = t0 + AKT;
            #pragma unroll
            for (int i = 0; i < 2; i++) {
                int lin = i*256 + tid;
                int r = lin >> 4, c = (lin & 15) * 8;
                long long goff = kbase + (long long)(t1+r)*KVDIM + c;
                cpa16(&Khi[nb + r*ALB + c], g_khi + goff);
                cpa16(&Klo[nb + r*ALB + c], g_klo + goff);
                cpa16(&Vhi[nb + r*ALB + c], g_vhi + goff);
                cpa16(&Vlo[nb + r*ALB + c], g_vlo + goff);
            }
            CP_COMMIT();
        }

        {
            wmma::fragment<wmma::accumulator,16,16,16,float> sacc0, sacc1;
            wmma::fill_fragment(sacc0, 0.f);
            wmma::fill_fragment(sacc1, 0.f);
            #pragma unroll
            for (int kk = 0; kk < HEAD_DIM; kk += 32) {
                wmma::fragment<wmma::matrix_a,16,16,16,bf16,wmma::row_major> a0h,a0l,a1h,a1l;
                wmma::fragment<wmma::matrix_b,16,16,16,bf16,wmma::col_major> b0h,b0l,b1h,b1l;
                wmma::load_matrix_sync(a0h, &qhi[smr*ALB + kk], ALB);
                wmma::load_matrix_sync(a0l, &qlo[smr*ALB + kk], ALB);
                wmma::load_matrix_sync(b0h, &Khi[cb + snc*ALB + kk], ALB);
                wmma::load_matrix_sync(b0l, &Klo[cb + snc*ALB + kk], ALB);
                wmma::load_matrix_sync(a1h, &qhi[smr*ALB + kk + 16], ALB);
                wmma::load_matrix_sync(a1l, &qlo[smr*ALB + kk + 16], ALB);
                wmma::load_matrix_sync(b1h, &Khi[cb + snc*ALB + kk + 16], ALB);
                wmma::load_matrix_sync(b1l, &Klo[cb + snc*ALB + kk + 16], ALB);
                wmma::mma_sync(sacc0, a0h, b0l, sacc0);
                wmma::mma_sync(sacc1, a1h, b1l, sacc1);
                wmma::mma_sync(sacc0, a0l, b0h, sacc0);
                wmma::mma_sync(sacc1, a1l, b1h, sacc1);
                wmma::mma_sync(sacc0, a0h, b0h, sacc0);
                wmma::mma_sync(sacc1, a1h, b1h, sacc1);
            }
            #pragma unroll
            for (int t = 0; t < sacc0.num_elements; t++) sacc0.x[t] += sacc1.x[t];
            wmma::store_matrix_sync(&sc[smr*SLD + snc], sacc0, SLD, wmma::mem_row_major);
        }
        __syncthreads();

        {
            int r = tid >> 2, sub = tid & 3;
            float sum = 0.f;
            #pragma unroll
            for (int cc = 0; cc < 8; cc++) {
                int c = sub*8 + cc;
                float p = (t0 + c <= q0 + r) ? __expf(sc[r*SLD + c] - SMAX_OFF) : 0.f;
                sum += p;
                bf16 ph, pl;
                split_bf16(p, ph, pl);
                phi[r*PLD + c] = ph;
                plo[r*PLD + c] = pl;
            }
            sum += __shfl_xor_sync(0xffffffffu, sum, 1);
            sum += __shfl_xor_sync(0xffffffffu, sum, 2);
            if (sub == 0) lsm[r] += sum;
        }
        __syncthreads();

        #pragma unroll
        for (int kk = 0; kk < AKT; kk += 16) {
            wmma::fragment<wmma::matrix_a,16,16,16,bf16,wmma::row_major> ahi, alo;
            wmma::load_matrix_sync(ahi, &phi[(mi*16)*PLD + kk], PLD);
            wmma::load_matrix_sync(alo, &plo[(mi*16)*PLD + kk], PLD);
            wmma::fragment<wmma::matrix_b,16,16,16,bf16,wmma::row_major> bhi[4], blo[4];
            #pragma unroll
            for (int nj = 0; nj < 4; nj++) {
                wmma::load_matrix_sync(bhi[nj], &Vhi[cb + kk*ALB + n0 + nj*16], ALB);
                wmma::load_matrix_sync(blo[nj], &Vlo[cb + kk*ALB + n0 + nj*16], ALB);
            }
            #pragma unroll
            for (int nj = 0; nj < 4; nj++)
                wmma::mma_sync(pacc[nj], ahi, blo[nj], pacc[nj]);
            #pragma unroll
            for (int nj = 0; nj < 4; nj++)
                wmma::mma_sync(pacc[nj], alo, bhi[nj], pacc[nj]);
            #pragma unroll
            for (int nj = 0; nj < 4; nj++)
                wmma::mma_sync(pacc[nj], ahi, bhi[nj], pacc[nj]);
        }
    }

    __syncthreads();
    #pragma unroll
    for (int nj = 0; nj < 4; nj++)
        wmma::store_matrix_sync(&cts[(mi*16)*CLD + n0 + nj*16], pacc[nj], CLD, wmma::mem_row_major);
    __syncthreads();

    #pragma unroll
    for (int i = 0; i < 8; i++) {
        int lin = i*256 + tid;
        int r = lin >> 5, c4 = (lin & 31) << 2;
        float inv = 1.f / lsm[r];
        float4 cv = *(float4*)&cts[r*CLD + c4];
        cv.x *= inv; cv.y *= inv; cv.z *= inv; cv.w *= inv;
        split_store4(cv, g_ctxhi, g_ctxlo, qoff + (long long)r*QDIM + c4);
    }
}

// ---------------- MoE routing ----------------
__global__ void reset_kernel() {
    if (threadIdx.x < N_EXP) g_counts[threadIdx.x] = 0;
}

__global__ void router_kernel(const float* __restrict__ h, const float* __restrict__ rw) {
    int warp = threadIdx.x >> 5, lane = threadIdx.x & 31;
    int t = blockIdx.x * 4 + warp;
    const float* hr = h + (long long)t * EMB;
    float lg[N_EXP];
    #pragma unroll
    for (int e = 0; e < N_EXP; e++) {
        float p = 0.f;
        for (int d = lane; d < EMB; d += 32) p += hr[d] * rw[e * EMB + d];
        #pragma unroll
        for (int o = 16; o; o >>= 1) p += __shfl_xor_sync(0xffffffffu, p, o);
        lg[e] = __shfl_sync(0xffffffffu, p, 0);
    }
    if (lane == 0) {
        int i1 = 0;
        #pragma unroll
        for (int e = 1; e < N_EXP; e++) if (lg[e] > lg[i1]) i1 = e;
        int i2 = -1;
        #pragma unroll
        for (int e = 0; e < N_EXP; e++) {
            if (e == i1) continue;
            if (i2 < 0 || lg[e] > lg[i2]) i2 = e;
        }
        float e1 = expf(lg[i2] - lg[i1]);
        float w0 = 1.f / (1.f + e1);
        float w1 = e1 / (1.f + e1);
        g_topk_idx[t*2]   = i1;  g_topk_idx[t*2+1] = i2;
        g_topk_w[t*2]     = w0;  g_topk_w[t*2+1]   = w1;
        atomicAdd(&g_counts[i1], 1);
        atomicAdd(&g_counts[i2], 1);
    }
}

__global__ void offsets_kernel() {
    if (threadIdx.x == 0) {
        int o = 0;
        for (int e = 0; e < N_EXP; e++) {
            g_off[e] = o; g_cursor[e] = o;
            o += g_counts[e];
        }
    }
}

__global__ void scatter_kernel() {
    int id = blockIdx.x * blockDim.x + threadIdx.x;
    if (id >= N_SLOT) return;
    int t = id >> 1;
    int e = g_topk_idx[id];
    int pos = atomicAdd(&g_cursor[e], 1);
    g_slot_token[pos] = t;
    g_slot_of[id] = pos;
}

// ---------------- combine ----------------
__global__ void combine_kernel(const float* __restrict__ x1, float* __restrict__ out) {
    int t = blockIdx.x;
    int d4 = threadIdx.x * 4;
    int s0 = g_slot_of[t*2], s1 = g_slot_of[t*2+1];
    float w0 = g_topk_w[t*2], w1 = g_topk_w[t*2+1];
    float4 a  = *(const float4*)(x1 + (long long)t * EMB + d4);
    float4 e0 = *(const float4*)(g_outslot + (long long)s0 * EMB + d4);
    float4 e1 = *(const float4*)(g_outslot + (long long)s1 * EMB + d4);
    float4 r;
    r.x = a.x + w0*e0.x + w1*e1.x;
    r.y = a.y + w0*e0.y + w1*e1.y;
    r.z = a.z + w0*e0.z + w1*e1.z;
    r.w = a.w + w0*e0.w + w1*e1.w;
    *(float4*)(out + (long long)t * EMB + d4) = r;
}

// ---------------- launch ----------------
extern "C" void kernel_launch(void* const* d_in, const int* in_sizes, int n_in,
                              void* d_out, int out_size) {
    const float* x        = (const float*)d_in[0];
    const int*   pos_ids  = (const int*)d_in[1];
    const float* norm1_w  = (const float*)d_in[3];
    const float* norm2_w  = (const float*)d_in[4];
    const float* qn_w     = (const float*)d_in[5];
    const float* kn_w     = (const float*)d_in[6];
    const float* q_w      = (const float*)d_in[7];
    const float* k_w      = (const float*)d_in[8];
    const float* v_w      = (const float*)d_in[9];
    const float* o_w      = (const float*)d_in[10];
    const float* router_w = (const float*)d_in[11];
    const float* gate_up  = (const float*)d_in[12];
    const float* down     = (const float*)d_in[13];
    float* out = (float*)d_out;

    bf16 *p_h1hi, *p_h1lo, *p_ctxhi, *p_ctxlo, *p_h2hi, *p_h2lo, *p_acthi, *p_actlo;
    bf16 *p_qhi, *p_qlo, *p_khi, *p_klo;
    float *p_qkv, *p_x1, *p_h2, *p_outslot;
    int *p_off, *p_cnt, *p_slot_token;
    cudaGetSymbolAddress((void**)&p_h1hi, g_h1hi);
    cudaGetSymbolAddress((void**)&p_h1lo, g_h1lo);
    cudaGetSymbolAddress((void**)&p_qkv, g_qkv);
    cudaGetSymbolAddress((void**)&p_qhi, g_qhi);
    cudaGetSymbolAddress((void**)&p_qlo, g_qlo);
    cudaGetSymbolAddress((void**)&p_khi, g_khi);
    cudaGetSymbolAddress((void**)&p_klo, g_klo);
    cudaGetSymbolAddress((void**)&p_ctxhi, g_ctxhi);
    cudaGetSymbolAddress((void**)&p_ctxlo, g_ctxlo);
    cudaGetSymbolAddress((void**)&p_x1, g_x1);
    cudaGetSymbolAddress((void**)&p_h2, g_h2);
    cudaGetSymbolAddress((void**)&p_h2hi, g_h2hi);
    cudaGetSymbolAddress((void**)&p_h2lo, g_h2lo);
    cudaGetSymbolAddress((void**)&p_acthi, g_acthi);
    cudaGetSymbolAddress((void**)&p_actlo, g_actlo);
    cudaGetSymbolAddress((void**)&p_outslot, g_outslot);
    cudaGetSymbolAddress((void**)&p_off, g_off);
    cudaGetSymbolAddress((void**)&p_cnt, g_counts);
    cudaGetSymbolAddress((void**)&p_slot_token, g_slot_token);

    static int smem_set = 0;
    if (!smem_set) {
        cudaFuncSetAttribute(attn_tc, cudaFuncAttributeMaxDynamicSharedMemorySize, ATTN_SMEM);
        cudaFuncSetAttribute(gemm_tc, cudaFuncAttributeMaxDynamicSharedMemorySize, GEMM_SMEM);
        smem_set = 1;
    }

    // 0) rope table
    rope_table_kernel<<<SEQ, 64>>>(pos_ids);

    // 1) pre-attention norm -> h1 hi/lo
    rmsnorm_kernel<<<T_TOK, 256>>>(x, norm1_w, p_h1hi, p_h1lo, nullptr);

    // 2) fused QKV projection (3-way B source)
    gemm_tc<<<dim3(QKVDIM/GBN, T_TOK/GBM, 1), 256, GEMM_SMEM>>>(
        p_h1hi, p_h1lo, q_w, k_w, v_w, QDIM, QDIM + KVDIM,
        p_qkv, T_TOK, QKVDIM, EMB,
        nullptr, nullptr, nullptr, nullptr, 0, 0);

    // 3) per-head RMSNorm + RoPE (warp-per-head) + V split
    qknorm_rope_kernel<<<T_TOK*N_HEADS/4, 128>>>(
        p_qkv, qn_w, 0, p_qhi, p_qlo, QDIM, 0.08838834764831845f, N_HEADS);
    qknorm_rope_kernel<<<T_TOK*N_KV/4, 128>>>(
        p_qkv, kn_w, QDIM, p_khi, p_klo, KVDIM, 1.0f, N_KV);
    vsplit_kernel<<<T_TOK, 128>>>();

    // 4) causal GQA flash attention -> ctx hi/lo
    attn_tc<<<dim3(SEQ/AQT, N_HEADS, BATCH), 256, ATTN_SMEM>>>();

    // 5) output projection + residual
    gemm_tc<<<dim3(EMB/GBN, T_TOK/GBM, 1), 256, GEMM_SMEM>>>(
        p_ctxhi, p_ctxlo, o_w, nullptr, nullptr, 0, 0,
        p_x1, T_TOK, EMB, QDIM,
        x, nullptr, nullptr, nullptr, 0, 0);

    // 6) pre-MoE norm -> h2 fp32 (router) + hi/lo (gemm)
    rmsnorm_kernel<<<T_TOK, 256>>>(p_x1, norm2_w, p_h2hi, p_h2lo, p_h2);

    // 7) routing (top-2) + expert grouping
    reset_kernel<<<1, 32>>>();
    router_kernel<<<T_TOK/4, 128>>>(p_h2, router_w);
    offsets_kernel<<<1, 32>>>();
    scatter_kernel<<<(N_SLOT + 255)/256, 256>>>();

    // 8) expert gate_up GEMM with fused SiLU -> act hi/lo (mode 1; permuted cols)
    gemm_tc<<<dim3((2*MOE_HID)/GBN, N_SLOT/GBM, N_EXP), 256, GEMM_SMEM>>>(
        p_h2hi, p_h2lo, gate_up, nullptr, nullptr, 0, 0,
        nullptr, N_SLOT, 2*MOE_HID, EMB,
        nullptr, p_off, p_cnt, p_slot_token, (long long)(2*MOE_HID)*EMB, 1);

    // 9) expert down GEMM -> outslot (mode 0)
    gemm_tc<<<dim3(EMB/GBN, N_SLOT/GBM, N_EXP), 256, GEMM_SMEM>>>(
        p_acthi, p_actlo, down, nullptr, nullptr, 0, 0,
        p_outslot, N_SLOT, EMB, MOE_HID,
        nullptr, p_off, p_cnt, nullptr, (long long)EMB*MOE_HID, 0);

    // 10) weighted combine + residual
    combine_kernel<<<T_TOK, 256>>>(p_x1, out);

    (void)in_sizes; (void)n_in; (void)out_size;
}

// round 16
// speedup vs baseline: 1.0046x; 1.0001x over previous
#include <cuda_runtime.h>
#include <cuda_bf16.h>
#include <mma.h>
#include <math.h>

using namespace nvcuda;

// ---------------- problem constants ----------------
#define EMB      1024
#define N_HEADS  16
#define N_KV     4
#define HEAD_DIM 128
#define N_EXP    8
#define TOP_K    2
#define MOE_HID  1024
#define BATCH    2
#define SEQ      2048
#define T_TOK    (BATCH*SEQ)          // 4096
#define QDIM     (N_HEADS*HEAD_DIM)   // 2048
#define KVDIM    (N_KV*HEAD_DIM)      // 512
#define QKVDIM   (QDIM + 2*KVDIM)     // 3072
#define N_SLOT   (T_TOK*TOP_K)        // 8192
#define EPSV     1e-6f

typedef __nv_bfloat16 bf16;

// ---------------- scratch (device globals; no allocation allowed) ----------------
__device__ bf16  g_h1hi[T_TOK*EMB],  g_h1lo[T_TOK*EMB];
__device__ float g_qkv[T_TOK*QKVDIM];
__device__ bf16  g_qhi[T_TOK*QDIM],  g_qlo[T_TOK*QDIM];
__device__ bf16  g_khi[T_TOK*KVDIM], g_klo[T_TOK*KVDIM];
__device__ bf16  g_vhi[T_TOK*KVDIM], g_vlo[T_TOK*KVDIM];
__device__ bf16  g_ctxhi[T_TOK*QDIM], g_ctxlo[T_TOK*QDIM];
__device__ float g_x1[T_TOK*EMB];
__device__ float g_h2[T_TOK*EMB];
__device__ bf16  g_h2hi[T_TOK*EMB],  g_h2lo[T_TOK*EMB];
__device__ bf16  g_acthi[N_SLOT*MOE_HID], g_actlo[N_SLOT*MOE_HID];
__device__ float g_outslot[N_SLOT*EMB];
__device__ float g_ropecos[SEQ*64], g_ropesin[SEQ*64];
__device__ int   g_topk_idx[N_SLOT];
__device__ float g_topk_w[N_SLOT];
__device__ int   g_counts[N_EXP];
__device__ int   g_off[N_EXP];
__device__ int   g_cursor[N_EXP];
__device__ int   g_slot_token[N_SLOT];
__device__ int   g_slot_of[N_SLOT];

// ---------------- bf16 hi/lo split helpers ----------------
__device__ __forceinline__ void split_bf16(float x, bf16& hi, bf16& lo) {
    hi = __float2bfloat16(x);
    lo = __float2bfloat16(x - __bfloat162float(hi));
}
__device__ __forceinline__ void split_store4(float4 v, bf16* hi, bf16* lo, long long idx) {
    bf16 h0,l0,h1,l1,h2,l2,h3,l3;
    split_bf16(v.x,h0,l0); split_bf16(v.y,h1,l1);
    split_bf16(v.z,h2,l2); split_bf16(v.w,h3,l3);
    __nv_bfloat162 hh0 = {h0,h1}, hh1 = {h2,h3};
    __nv_bfloat162 ll0 = {l0,l1}, ll1 = {l2,l3};
    ((__nv_bfloat162*)(hi + idx))[0] = hh0;
    ((__nv_bfloat162*)(hi + idx))[1] = hh1;
    ((__nv_bfloat162*)(lo + idx))[0] = ll0;
    ((__nv_bfloat162*)(lo + idx))[1] = ll1;
}

// ---------------- cp.async helpers ----------------
__device__ __forceinline__ void cpa16(void* dst, const void* src) {
    unsigned s = (unsigned)__cvta_generic_to_shared(dst);
    asm volatile("cp.async.cg.shared.global [%0], [%1], 16;" :: "r"(s), "l"(src));
}
#define CP_COMMIT() asm volatile("cp.async.commit_group;")
#define CP_WAIT0()  asm volatile("cp.async.wait_group 0;" ::: "memory")

// ---------------- block reduce (sum, broadcast) ----------------
__device__ __forceinline__ float blockReduceSum(float v) {
    __shared__ float sh[32];
    int lane = threadIdx.x & 31;
    int wid  = threadIdx.x >> 5;
    int nw   = blockDim.x >> 5;
    #pragma unroll
    for (int o = 16; o; o >>= 1) v += __shfl_xor_sync(0xffffffffu, v, o);
    if (lane == 0) sh[wid] = v;
    __syncthreads();
    if (threadIdx.x == 0) {
        float s = 0.f;
        for (int i = 0; i < nw; i++) s += sh[i];
        sh[0] = s;
    }
    __syncthreads();
    float r = sh[0];
    __syncthreads();
    return r;
}

// ---------------- rope table ----------------
__global__ void rope_table_kernel(const int* __restrict__ pos_ids) {
    int s = blockIdx.x, i = threadIdx.x;
    float inv = exp2f(-(float)i * (13.287712379549449f / 64.0f));
    float ang = (float)pos_ids[s] * inv;
    float sn, cs;
    sincosf(ang, &sn, &cs);
    g_ropecos[s*64 + i] = cs;
    g_ropesin[s*64 + i] = sn;
}

// ---------------- RMSNorm over EMB=1024, writes hi/lo (+ optional fp32) ----------------
__global__ void rmsnorm_kernel(const float* __restrict__ x, const float* __restrict__ w,
                               bf16* __restrict__ ohi, bf16* __restrict__ olo,
                               float* __restrict__ ofp) {
    int t = blockIdx.x;
    int d4 = threadIdx.x * 4;
    const float* xr = x + (long long)t * EMB;
    float4 v = *(const float4*)(xr + d4);
    long long idx = (long long)t * EMB + d4;
    float ss = v.x*v.x + v.y*v.y + v.z*v.z + v.w*v.w;
    ss = blockReduceSum(ss);
    float scale = rsqrtf(ss * (1.0f / EMB) + EPSV);
    float4 wv = *(const float4*)(w + d4);
    float4 r;
    r.x = v.x*scale*wv.x; r.y = v.y*scale*wv.y;
    r.z = v.z*scale*wv.z; r.w = v.w*scale*wv.w;
    split_store4(r, ohi, olo, idx);
    if (ofp) *(float4*)(ofp + idx) = r;
}

// ---------------- warp-level per-head RMSNorm + RoPE (device helper) ----------------
__device__ __forceinline__ void norm_rope_warp(int gw, int lane, const float* __restrict__ w,
                                               int colOff, bf16* __restrict__ ohi,
                                               bf16* __restrict__ olo, int outStride,
                                               float outScale, int H) {
    int t = gw / H, h = gw % H;
    const float* base = g_qkv + (long long)t * QKVDIM + colOff + h * HEAD_DIM;
    float4 v = *(const float4*)(base + lane * 4);
    float ss = v.x*v.x + v.y*v.y + v.z*v.z + v.w*v.w;
    #pragma unroll
    for (int o = 16; o; o >>= 1) ss += __shfl_xor_sync(0xffffffffu, ss, o);
    float scale = rsqrtf(ss * (1.0f / HEAD_DIM) + EPSV);
    float4 wv = *(const float4*)(w + lane * 4);
    float4 nv;
    nv.x = v.x*scale*wv.x; nv.y = v.y*scale*wv.y;
    nv.z = v.z*scale*wv.z; nv.w = v.w*scale*wv.w;
    float ox = __shfl_xor_sync(0xffffffffu, nv.x, 16);
    float oy = __shfl_xor_sync(0xffffffffu, nv.y, 16);
    float oz = __shfl_xor_sync(0xffffffffu, nv.z, 16);
    float ow = __shfl_xor_sync(0xffffffffu, nv.w, 16);
    float sgn = (lane < 16) ? -1.f : 1.f;
    int s = t & (SEQ - 1);
    int i0 = (lane & 15) * 4;
    float4 cs = *(const float4*)(g_ropecos + s*64 + i0);
    float4 sn = *(const float4*)(g_ropesin + s*64 + i0);
    float4 r;
    r.x = (nv.x*cs.x + sgn*ox*sn.x) * outScale;
    r.y = (nv.y*cs.y + sgn*oy*sn.y) * outScale;
    r.z = (nv.z*cs.z + sgn*oz*sn.z) * outScale;
    r.w = (nv.w*cs.w + sgn*ow*sn.w) * outScale;
    split_store4(r, ohi, olo, (long long)t * outStride + h * HEAD_DIM + lane * 4);
}

// ---------------- merged post-QKV: Q norm+rope, K norm+rope, V split (one launch) ----------
#define NQW (T_TOK*N_HEADS)           // 65536 Q warps
#define NKW (T_TOK*N_KV)              // 16384 K warps
#define NVW (T_TOK*4)                 // 16384 V warps (4 quarters/token)
#define QKV_POST_BLOCKS ((NQW + NKW + NVW)/4)

__global__ void qkv_post_kernel(const float* __restrict__ qn_w, const float* __restrict__ kn_w) {
    int gw = blockIdx.x * 4 + (threadIdx.x >> 5);
    int lane = threadIdx.x & 31;
    if (gw < NQW) {
        norm_rope_warp(gw, lane, qn_w, 0, g_qhi, g_qlo, QDIM, 0.08838834764831845f, N_HEADS);
    } else if (gw < NQW + NKW) {
        norm_rope_warp(gw - NQW, lane, kn_w, QDIM, g_khi, g_klo, KVDIM, 1.0f, N_KV);
    } else {
        int vw = gw - NQW - NKW;
        int t = vw >> 2, qd = vw & 3;
        float4 v = *(const float4*)(g_qkv + (long long)t*QKVDIM + QDIM + KVDIM + qd*128 + lane*4);
        split_store4(v, g_vhi, g_vlo, (long long)t*KVDIM + qd*128 + lane*4);
    }
}

// ---------------- bf16x3 GEMM (R10 core) with optional fused SiLU epilogue ----------------
#define GBM 128
#define GBN 128
#define GBK 32
#define BKP 40
#define GEMM_SMEM (8*GBM*BKP*2)   // 81920 B
#define STLD 132                  // epilogue stage ld (fp32)

__global__ __launch_bounds__(256, 2)
void gemm_tc(const bf16* __restrict__ Ahi, const bf16* __restrict__ Alo,
             const float* __restrict__ Bsrc,
             const float* __restrict__ Bsrc2, const float* __restrict__ Bsrc3,
             int nSplit1, int nSplit2,
             float* __restrict__ C, int Mtotal, int N, int K,
             const float* __restrict__ addres,
             const int* __restrict__ seg_off, const int* __restrict__ seg_cnt,
             const int* __restrict__ rowidx, long long strideB, int mode) {
    extern __shared__ char gsm[];
    bf16* sAhi = (bf16*)gsm;
    bf16* sAlo = sAhi + 2*GBM*BKP;
    bf16* sBhi = sAlo + 2*GBM*BKP;
    bf16* sBlo = sBhi + 2*GBN*BKP;

    int z = blockIdx.z;
    int mbase = 0, mcnt = Mtotal;
    if (seg_off) { mbase = seg_off[z]; mcnt = seg_cnt[z]; }
    int tm0 = blockIdx.y * GBM;
    if (tm0 >= mcnt) return;
    int tn0 = blockIdx.x * GBN;

    int tid = threadIdx.x;
    int wid = tid >> 5;
    int lane = tid & 31;
    int wm = wid & 3;
    int wn = wid >> 2;

    int lrow = tid >> 1;
    int lc0 = (tid & 1) * 16;

    int arowLocal = tm0 + lrow;
    bool avalid = (arowLocal < mcnt);
    long long arow = 0;
    if (avalid) arow = rowidx ? (long long)rowidx[mbase + arowLocal] : (long long)(mbase + arowLocal);
    const bf16* Ah = Ahi + arow * (long long)K + lc0;
    const bf16* Al = Alo + arow * (long long)K + lc0;

    const float* Bload;
    {
        int n = tn0 + lrow;
        const float* base = Bsrc + (long long)z * strideB;
        long long nr = n;
        if (Bsrc2 && n >= nSplit1) {
            if (n < nSplit2) { base = Bsrc2; nr = n - nSplit1; }
            else             { base = Bsrc3; nr = n - nSplit2; }
        } else if (mode == 1) {
            int j = ((n >> 7) << 6) + (n & 63);
            nr = (n & 64) ? (MOE_HID + j) : j;
        }
        Bload = base + nr * (long long)K + lc0;
    }

    wmma::fragment<wmma::accumulator,16,16,16,float> acc[2][4];
    #pragma unroll
    for (int i = 0; i < 2; i++)
        #pragma unroll
        for (int j = 0; j < 4; j++) wmma::fill_fragment(acc[i][j], 0.f);

    int nIter = K / GBK;
    union Pack { bf16 b[8]; uint4 u; };
    int sOff = lrow*BKP + lc0;

    {
        cpa16(&sAhi[sOff],     Ah);
        cpa16(&sAhi[sOff + 8], Ah + 8);
        cpa16(&sAlo[sOff],     Al);
        cpa16(&sAlo[sOff + 8], Al + 8);
        CP_COMMIT();
        float4 b0 = *(const float4*)(Bload);
        float4 b1 = *(const float4*)(Bload+4);
        float4 b2 = *(const float4*)(Bload+8);
        float4 b3 = *(const float4*)(Bload+12);
        float bfv[16] = {b0.x,b0.y,b0.z,b0.w,b1.x,b1.y,b1.z,b1.w,
                         b2.x,b2.y,b2.z,b2.w,b3.x,b3.y,b3.z,b3.w};
        Pack Bh0, Bl0, Bh1, Bl1;
        #pragma unroll
        for (int e = 0; e < 8; e++) {
            split_bf16(bfv[e],   Bh0.b[e], Bl0.b[e]);
            split_bf16(bfv[e+8], Bh1.b[e], Bl1.b[e]);
        }
        *(uint4*)&sBhi[sOff]     = Bh0.u;
        *(uint4*)&sBhi[sOff + 8] = Bh1.u;
        *(uint4*)&sBlo[sOff]     = Bl0.u;
        *(uint4*)&sBlo[sOff + 8] = Bl1.u;
        CP_WAIT0();
    }
    __syncthreads();

    for (int it = 0; it < nIter; it++) {
        int cb = (it & 1) * GBM * BKP;
        int nb = ((it+1) & 1) * GBM * BKP;
        bool hasNext = (it + 1 < nIter);
        float4 b0, b1, b2, b3;
        if (hasNext) {
            int ko = (it+1)*GBK;
            cpa16(&sAhi[nb + sOff],     Ah + ko);
            cpa16(&sAhi[nb + sOff + 8], Ah + ko + 8);
            cpa16(&sAlo[nb + sOff],     Al + ko);
            cpa16(&sAlo[nb + sOff + 8], Al + ko + 8);
            CP_COMMIT();
            b0 = *(const float4*)(Bload + ko);
            b1 = *(const float4*)(Bload + ko + 4);
            b2 = *(const float4*)(Bload + ko + 8);
            b3 = *(const float4*)(Bload + ko + 12);
        }
        #pragma unroll
        for (int kk = 0; kk < GBK; kk += 16) {
            wmma::fragment<wmma::matrix_a,16,16,16,bf16,wmma::row_major> ahi[2], alo[2];
            #pragma unroll
            for (int i = 0; i < 2; i++) {
                wmma::load_matrix_sync(ahi[i], &sAhi[cb + (wm*32 + i*16)*BKP + kk], BKP);
                wmma::load_matrix_sync(alo[i], &sAlo[cb + (wm*32 + i*16)*BKP + kk], BKP);
            }
            #pragma unroll
            for (int jp = 0; jp < 2; jp++) {
                wmma::fragment<wmma::matrix_b,16,16,16,bf16,wmma::col_major> bhf[2], blf[2];
                #pragma unroll
                for (int jj = 0; jj < 2; jj++) {
                    int j = jp*2 + jj;
                    wmma::load_matrix_sync(bhf[jj], &sBhi[cb + (wn*64 + j*16)*BKP + kk], BKP);
                    wmma::load_matrix_sync(blf[jj], &sBlo[cb + (wn*64 + j*16)*BKP + kk], BKP);
                }
                #pragma unroll
                for (int jj = 0; jj < 2; jj++)
                    #pragma unroll
                    for (int i = 0; i < 2; i++)
                        wmma::mma_sync(acc[i][jp*2+jj], ahi[i], blf[jj], acc[i][jp*2+jj]);
                #pragma unroll
                for (int jj = 0; jj < 2; jj++)
                    #pragma unroll
                    for (int i = 0; i < 2; i++)
                        wmma::mma_sync(acc[i][jp*2+jj], alo[i], bhf[jj], acc[i][jp*2+jj]);
                #pragma unroll
                for (int jj = 0; jj < 2; jj++)
                    #pragma unroll
                    for (int i = 0; i < 2; i++)
                        wmma::mma_sync(acc[i][jp*2+jj], ahi[i], bhf[jj], acc[i][jp*2+jj]);
            }
        }
        if (hasNext) {
            float bfv[16] = {b0.x,b0.y,b0.z,b0.w,b1.x,b1.y,b1.z,b1.w,
                             b2.x,b2.y,b2.z,b2.w,b3.x,b3.y,b3.z,b3.w};
            Pack Bh0, Bl0, Bh1, Bl1;
            #pragma unroll
            for (int e = 0; e < 8; e++) {
                split_bf16(bfv[e],   Bh0.b[e], Bl0.b[e]);
                split_bf16(bfv[e+8], Bh1.b[e], Bl1.b[e]);
            }
            *(uint4*)&sBhi[nb + sOff]     = Bh0.u;
            *(uint4*)&sBhi[nb + sOff + 8] = Bh1.u;
            *(uint4*)&sBlo[nb + sOff]     = Bl0.u;
            *(uint4*)&sBlo[nb + sOff + 8] = Bl1.u;
            CP_WAIT0();
        }
        __syncthreads();
    }

    if (mode == 0) {
        bool full = (tm0 + GBM <= mcnt);
        if (full) {
            #pragma unroll
            for (int i = 0; i < 2; i++) {
                int grow = tm0 + wm*32 + i*16;
                #pragma unroll
                for (int j = 0; j < 4; j++) {
                    long long off = ((long long)(mbase + grow))*N + tn0 + wn*64 + j*16;
                    if (addres) {
                        wmma::fragment<wmma::accumulator,16,16,16,float> rf;
                        wmma::load_matrix_sync(rf, addres + off, N, wmma::mem_row_major);
                        #pragma unroll
                        for (int t = 0; t < rf.num_elements; t++) acc[i][j].x[t] += rf.x[t];
                    }
                    wmma::store_matrix_sync(C + off, acc[i][j], N, wmma::mem_row_major);
                }
            }
        } else {
            __syncthreads();
            float* stage = (float*)gsm + wid * 320;
            #pragma unroll
            for (int i = 0; i < 2; i++) {
                int growb = tm0 + wm*32 + i*16;
                #pragma unroll
                for (int j = 0; j < 4; j++) {
                    wmma::store_matrix_sync(stage, acc[i][j], 20, wmma::mem_row_major);
                    __syncwarp();
                    int gc0 = tn0 + wn*64 + j*16;
                    #pragma unroll
                    for (int e = 0; e < 8; e++) {
                        int idx = e*32 + lane;
                        int r = idx >> 4, c = idx & 15;
                        int grow = growb + r;
                        if (grow < mcnt) {
                            long long off = ((long long)(mbase + grow))*N + gc0 + c;
                            float vv = stage[r*20 + c];
                            if (addres) vv += addres[off];
                            C[off] = vv;
                        }
                    }
                    __syncwarp();
                }
            }
        }
    } else {
        // fused SiLU epilogue: stage full 128x128 tile in smem
        __syncthreads();
        float* stage = (float*)gsm;    // 128 x STLD fp32 = 67584 B < 81920
        #pragma unroll
        for (int i = 0; i < 2; i++)
            #pragma unroll
            for (int j = 0; j < 4; j++)
                wmma::store_matrix_sync(&stage[(wm*32 + i*16)*STLD + wn*64 + j*16],
                                        acc[i][j], STLD, wmma::mem_row_major);
        __syncthreads();
        int j0 = blockIdx.x * 64;
        #pragma unroll
        for (int k = 0; k < 32; k++) {
            int lin = k*256 + tid;
            int r = lin >> 6, c = lin & 63;
            if (tm0 + r < mcnt) {
                long long slot = mbase + tm0 + r;
                float gt = stage[r*STLD + c];
                float up = stage[r*STLD + 64 + c];
                float a = gt / (1.f + __expf(-gt)) * up;
                bf16 hh, ll;
                split_bf16(a, hh, ll);
                g_acthi[slot*MOE_HID + j0 + c] = hh;
                g_actlo[slot*MOE_HID + j0 + c] = ll;
            }
        }
    }
}

// ---------------- attention (R10): fixed-offset softmax, register ctx, cp.async KV ----------------
#define AQT 64
#define AKT 32
#define ALB 136
#define CLD 132
#define SLD 36
#define PLD 40
#define SMAX_OFF 12.0f
#define OF_QHI 0
#define OF_QLO (OF_QHI + AQT*ALB*2)
#define OF_KHI (OF_QLO + AQT*ALB*2)
#define OF_KLO (OF_KHI + 2*AKT*ALB*2)
#define OF_VHI (OF_KLO + 2*AKT*ALB*2)
#define OF_VLO (OF_VHI + 2*AKT*ALB*2)
#define OF_SC  (OF_VLO + 2*AKT*ALB*2)
#define OF_PHI (OF_SC  + AQT*SLD*4)
#define OF_PLO (OF_PHI + AQT*PLD*2)
#define OF_LS  (OF_PLO + AQT*PLD*2)
#define ATTN_SMEM (OF_LS + AQT*4)

__global__ __launch_bounds__(256)
void attn_tc() {
    extern __shared__ char asm_[];
    bf16* qhi = (bf16*)(asm_ + OF_QHI);
    bf16* qlo = (bf16*)(asm_ + OF_QLO);
    bf16* Khi = (bf16*)(asm_ + OF_KHI);
    bf16* Klo = (bf16*)(asm_ + OF_KLO);
    bf16* Vhi = (bf16*)(asm_ + OF_VHI);
    bf16* Vlo = (bf16*)(asm_ + OF_VLO);
    float* sc  = (float*)(asm_ + OF_SC);
    bf16* phi = (bf16*)(asm_ + OF_PHI);
    bf16* plo = (bf16*)(asm_ + OF_PLO);
    float* lsm = (float*)(asm_ + OF_LS);
    float* cts = (float*)(asm_ + OF_KHI);   // alias: used only after KV loop

    int q0 = SEQ - AQT - blockIdx.x * AQT;
    int h = blockIdx.y, b = blockIdx.z;
    int tid = threadIdx.x;
    int wid = tid >> 5;

    long long qoff = ((long long)b*SEQ + q0)*QDIM + (long long)h*HEAD_DIM;
    #pragma unroll
    for (int i = 0; i < 4; i++) {
        int lin = i*256 + tid;
        int r = lin >> 4, c = (lin & 15) * 8;
        *(uint4*)&qhi[r*ALB + c] = *(const uint4*)(g_qhi + qoff + (long long)r*QDIM + c);
        *(uint4*)&qlo[r*ALB + c] = *(const uint4*)(g_qlo + qoff + (long long)r*QDIM + c);
    }
    if (tid < AQT) lsm[tid] = 0.f;

    int kvh = h >> 2;
    long long kbase = (long long)b*SEQ*KVDIM + (long long)kvh*HEAD_DIM;

    int nT = q0 / AKT + 2;

    #pragma unroll
    for (int i = 0; i < 2; i++) {
        int lin = i*256 + tid;
        int r = lin >> 4, c = (lin & 15) * 8;
        long long goff = kbase + (long long)r*KVDIM + c;
        cpa16(&Khi[r*ALB + c], g_khi + goff);
        cpa16(&Klo[r*ALB + c], g_klo + goff);
        cpa16(&Vhi[r*ALB + c], g_vhi + goff);
        cpa16(&Vlo[r*ALB + c], g_vlo + goff);
    }
    CP_COMMIT();

    int mi = wid >> 1;
    int n0 = (wid & 1) * 64;
    wmma::fragment<wmma::accumulator,16,16,16,float> pacc[4];
    #pragma unroll
    for (int nj = 0; nj < 4; nj++) wmma::fill_fragment(pacc[nj], 0.f);

    int smr = (wid >> 1) * 16, snc = (wid & 1) * 16;

    for (int it = 0; it < nT; it++) {
        int t0 = it * AKT;
        int cb = (it & 1) * AKT * ALB;
        CP_WAIT0();
        __syncthreads();
        if (it + 1 < nT) {
            int nb = ((it+1) & 1) * AKT * ALB;
            int t1 = t0 + AKT;
            #pragma unroll
            for (int i = 0; i < 2; i++) {
                int lin = i*256 + tid;
                int r = lin >> 4, c = (lin & 15) * 8;
                long long goff = kbase + (long long)(t1+r)*KVDIM + c;
                cpa16(&Khi[nb + r*ALB + c], g_khi + goff);
                cpa16(&Klo[nb + r*ALB + c], g_klo + goff);
                cpa16(&Vhi[nb + r*ALB + c], g_vhi + goff);
                cpa16(&Vlo[nb + r*ALB + c], g_vlo + goff);
            }
            CP_COMMIT();
        }

        {
            wmma::fragment<wmma::accumulator,16,16,16,float> sacc0, sacc1;
            wmma::fill_fragment(sacc0, 0.f);
            wmma::fill_fragment(sacc1, 0.f);
            #pragma unroll
            for (int kk = 0; kk < HEAD_DIM; kk += 32) {
                wmma::fragment<wmma::matrix_a,16,16,16,bf16,wmma::row_major> a0h,a0l,a1h,a1l;
                wmma::fragment<wmma::matrix_b,16,16,16,bf16,wmma::col_major> b0h,b0l,b1h,b1l;
                wmma::load_matrix_sync(a0h, &qhi[smr*ALB + kk], ALB);
                wmma::load_matrix_sync(a0l, &qlo[smr*ALB + kk], ALB);
                wmma::load_matrix_sync(b0h, &Khi[cb + snc*ALB + kk], ALB);
                wmma::load_matrix_sync(b0l, &Klo[cb + snc*ALB + kk], ALB);
                wmma::load_matrix_sync(a1h, &qhi[smr*ALB + kk + 16], ALB);
                wmma::load_matrix_sync(a1l, &qlo[smr*ALB + kk + 16], ALB);
                wmma::load_matrix_sync(b1h, &Khi[cb + snc*ALB + kk + 16], ALB);
                wmma::load_matrix_sync(b1l, &Klo[cb + snc*ALB + kk + 16], ALB);
                wmma::mma_sync(sacc0, a0h, b0l, sacc0);
                wmma::mma_sync(sacc1, a1h, b1l, sacc1);
                wmma::mma_sync(sacc0, a0l, b0h, sacc0);
                wmma::mma_sync(sacc1, a1l, b1h, sacc1);
                wmma::mma_sync(sacc0, a0h, b0h, sacc0);
                wmma::mma_sync(sacc1, a1h, b1h, sacc1);
            }
            #pragma unroll
            for (int t = 0; t < sacc0.num_elements; t++) sacc0.x[t] += sacc1.x[t];
            wmma::store_matrix_sync(&sc[smr*SLD + snc], sacc0, SLD, wmma::mem_row_major);
        }
        __syncthreads();

        {
            int r = tid >> 2, sub = tid & 3;
            float sum = 0.f;
            #pragma unroll
            for (int cc = 0; cc < 8; cc++) {
                int c = sub*8 + cc;
                float p = (t0 + c <= q0 + r) ? __expf(sc[r*SLD + c] - SMAX_OFF) : 0.f;
                sum += p;
                bf16 ph, pl;
                split_bf16(p, ph, pl);
                phi[r*PLD + c] = ph;
                plo[r*PLD + c] = pl;
            }
            sum += __shfl_xor_sync(0xffffffffu, sum, 1);
            sum += __shfl_xor_sync(0xffffffffu, sum, 2);
            if (sub == 0) lsm[r] += sum;
        }
        __syncthreads();

        #pragma unroll
        for (int kk = 0; kk < AKT; kk += 16) {
            wmma::fragment<wmma::matrix_a,16,16,16,bf16,wmma::row_major> ahi, alo;
            wmma::load_matrix_sync(ahi, &phi[(mi*16)*PLD + kk], PLD);
            wmma::load_matrix_sync(alo, &plo[(mi*16)*PLD + kk], PLD);
            wmma::fragment<wmma::matrix_b,16,16,16,bf16,wmma::row_major> bhi[4], blo[4];
            #pragma unroll
            for (int nj = 0; nj < 4; nj++) {
                wmma::load_matrix_sync(bhi[nj], &Vhi[cb + kk*ALB + n0 + nj*16], ALB);
                wmma::load_matrix_sync(blo[nj], &Vlo[cb + kk*ALB + n0 + nj*16], ALB);
            }
            #pragma unroll
            for (int nj = 0; nj < 4; nj++)
                wmma::mma_sync(pacc[nj], ahi, blo[nj], pacc[nj]);
            #pragma unroll
            for (int nj = 0; nj < 4; nj++)
                wmma::mma_sync(pacc[nj], alo, bhi[nj], pacc[nj]);
            #pragma unroll
            for (int nj = 0; nj < 4; nj++)
                wmma::mma_sync(pacc[nj], ahi, bhi[nj], pacc[nj]);
        }
    }

    __syncthreads();
    #pragma unroll
    for (int nj = 0; nj < 4; nj++)
        wmma::store_matrix_sync(&cts[(mi*16)*CLD + n0 + nj*16], pacc[nj], CLD, wmma::mem_row_major);
    __syncthreads();

    #pragma unroll
    for (int i = 0; i < 8; i++) {
        int lin = i*256 + tid;
        int r = lin >> 5, c4 = (lin & 31) << 2;
        float inv = 1.f / lsm[r];
        float4 cv = *(float4*)&cts[r*CLD + c4];
        cv.x *= inv; cv.y *= inv; cv.z *= inv; cv.w *= inv;
        split_store4(cv, g_ctxhi, g_ctxlo, qoff + (long long)r*QDIM + c4);
    }
}

// ---------------- MoE routing ----------------
__global__ void reset_kernel() {
    if (threadIdx.x < N_EXP) g_counts[threadIdx.x] = 0;
}

__global__ void router_kernel(const float* __restrict__ h, const float* __restrict__ rw) {
    int warp = threadIdx.x >> 5, lane = threadIdx.x & 31;
    int t = blockIdx.x * 4 + warp;
    const float* hr = h + (long long)t * EMB;
    float lg[N_EXP];
    #pragma unroll
    for (int e = 0; e < N_EXP; e++) {
        float p = 0.f;
        for (int d = lane; d < EMB; d += 32) p += hr[d] * rw[e * EMB + d];
        #pragma unroll
        for (int o = 16; o; o >>= 1) p += __shfl_xor_sync(0xffffffffu, p, o);
        lg[e] = __shfl_sync(0xffffffffu, p, 0);
    }
    if (lane == 0) {
        int i1 = 0;
        #pragma unroll
        for (int e = 1; e < N_EXP; e++) if (lg[e] > lg[i1]) i1 = e;
        int i2 = -1;
        #pragma unroll
        for (int e = 0; e < N_EXP; e++) {
            if (e == i1) continue;
            if (i2 < 0 || lg[e] > lg[i2]) i2 = e;
        }
        float e1 = expf(lg[i2] - lg[i1]);
        float w0 = 1.f / (1.f + e1);
        float w1 = e1 / (1.f + e1);
        g_topk_idx[t*2]   = i1;  g_topk_idx[t*2+1] = i2;
        g_topk_w[t*2]     = w0;  g_topk_w[t*2+1]   = w1;
        atomicAdd(&g_counts[i1], 1);
        atomicAdd(&g_counts[i2], 1);
    }
}

__global__ void offsets_kernel() {
    if (threadIdx.x == 0) {
        int o = 0;
        for (int e = 0; e < N_EXP; e++) {
            g_off[e] = o; g_cursor[e] = o;
            o += g_counts[e];
        }
    }
}

__global__ void scatter_kernel() {
    int id = blockIdx.x * blockDim.x + threadIdx.x;
    if (id >= N_SLOT) return;
    int t = id >> 1;
    int e = g_topk_idx[id];
    int pos = atomicAdd(&g_cursor[e], 1);
    g_slot_token[pos] = t;
    g_slot_of[id] = pos;
}

// ---------------- combine ----------------
__global__ void combine_kernel(const float* __restrict__ x1, float* __restrict__ out) {
    int t = blockIdx.x;
    int d4 = threadIdx.x * 4;
    int s0 = g_slot_of[t*2], s1 = g_slot_of[t*2+1];
    float w0 = g_topk_w[t*2], w1 = g_topk_w[t*2+1];
    float4 a  = *(const float4*)(x1 + (long long)t * EMB + d4);
    float4 e0 = *(const float4*)(g_outslot + (long long)s0 * EMB + d4);
    float4 e1 = *(const float4*)(g_outslot + (long long)s1 * EMB + d4);
    float4 r;
    r.x = a.x + w0*e0.x + w1*e1.x;
    r.y = a.y + w0*e0.y + w1*e1.y;
    r.z = a.z + w0*e0.z + w1*e1.z;
    r.w = a.w + w0*e0.w + w1*e1.w;
    *(float4*)(out + (long long)t * EMB + d4) = r;
}

// ---------------- launch ----------------
extern "C" void kernel_launch(void* const* d_in, const int* in_sizes, int n_in,
                              void* d_out, int out_size) {
    const float* x        = (const float*)d_in[0];
    const int*   pos_ids  = (const int*)d_in[1];
    const float* norm1_w  = (const float*)d_in[3];
    const float* norm2_w  = (const float*)d_in[4];
    const float* qn_w     = (const float*)d_in[5];
    const float* kn_w     = (const float*)d_in[6];
    const float* q_w      = (const float*)d_in[7];
    const float* k_w      = (const float*)d_in[8];
    const float* v_w      = (const float*)d_in[9];
    const float* o_w      = (const float*)d_in[10];
    const float* router_w = (const float*)d_in[11];
    const float* gate_up  = (const float*)d_in[12];
    const float* down     = (const float*)d_in[13];
    float* out = (float*)d_out;

    bf16 *p_h1hi, *p_h1lo, *p_ctxhi, *p_ctxlo, *p_h2hi, *p_h2lo, *p_acthi, *p_actlo;
    float *p_x1, *p_h2, *p_outslot;
    int *p_off, *p_cnt, *p_slot_token;
    cudaGetSymbolAddress((void**)&p_h1hi, g_h1hi);
    cudaGetSymbolAddress((void**)&p_h1lo, g_h1lo);
    cudaGetSymbolAddress((void**)&p_ctxhi, g_ctxhi);
    cudaGetSymbolAddress((void**)&p_ctxlo, g_ctxlo);
    cudaGetSymbolAddress((void**)&p_x1, g_x1);
    cudaGetSymbolAddress((void**)&p_h2, g_h2);
    cudaGetSymbolAddress((void**)&p_h2hi, g_h2hi);
    cudaGetSymbolAddress((void**)&p_h2lo, g_h2lo);
    cudaGetSymbolAddress((void**)&p_acthi, g_acthi);
    cudaGetSymbolAddress((void**)&p_actlo, g_actlo);
    cudaGetSymbolAddress((void**)&p_outslot, g_outslot);
    cudaGetSymbolAddress((void**)&p_off, g_off);
    cudaGetSymbolAddress((void**)&p_cnt, g_counts);
    cudaGetSymbolAddress((void**)&p_slot_token, g_slot_token);

    float* p_qkv;
    cudaGetSymbolAddress((void**)&p_qkv, g_qkv);

    static int smem_set = 0;
    if (!smem_set) {
        cudaFuncSetAttribute(attn_tc, cudaFuncAttributeMaxDynamicSharedMemorySize, ATTN_SMEM);
        cudaFuncSetAttribute(gemm_tc, cudaFuncAttributeMaxDynamicSharedMemorySize, GEMM_SMEM);
        smem_set = 1;
    }

    // 0) rope table
    rope_table_kernel<<<SEQ, 64>>>(pos_ids);

    // 1) pre-attention norm -> h1 hi/lo
    rmsnorm_kernel<<<T_TOK, 256>>>(x, norm1_w, p_h1hi, p_h1lo, nullptr);

    // 2) fused QKV projection (3-way B source)
    gemm_tc<<<dim3(QKVDIM/GBN, T_TOK/GBM, 1), 256, GEMM_SMEM>>>(
        p_h1hi, p_h1lo, q_w, k_w, v_w, QDIM, QDIM + KVDIM,
        p_qkv, T_TOK, QKVDIM, EMB,
        nullptr, nullptr, nullptr, nullptr, 0, 0);

    // 3) merged post-QKV: Q norm+rope, K norm+rope, V split (one launch)
    qkv_post_kernel<<<QKV_POST_BLOCKS, 128>>>(qn_w, kn_w);

    // 4) causal GQA flash attention -> ctx hi/lo
    attn_tc<<<dim3(SEQ/AQT, N_HEADS, BATCH), 256, ATTN_SMEM>>>();

    // 5) output projection + residual
    gemm_tc<<<dim3(EMB/GBN, T_TOK/GBM, 1), 256, GEMM_SMEM>>>(
        p_ctxhi, p_ctxlo, o_w, nullptr, nullptr, 0, 0,
        p_x1, T_TOK, EMB, QDIM,
        x, nullptr, nullptr, nullptr, 0, 0);

    // 6) pre-MoE norm -> h2 fp32 (router) + hi/lo (gemm)
    rmsnorm_kernel<<<T_TOK, 256>>>(p_x1, norm2_w, p_h2hi, p_h2lo, p_h2);

    // 7) routing (top-2) + expert grouping
    reset_kernel<<<1, 32>>>();
    router_kernel<<<T_TOK/4, 128>>>(p_h2, router_w);
    offsets_kernel<<<1, 32>>>();
    scatter_kernel<<<(N_SLOT + 255)/256, 256>>>();

    // 8) expert gate_up GEMM with fused SiLU -> act hi/lo (mode 1; permuted cols)
    gemm_tc<<<dim3((2*MOE_HID)/GBN, N_SLOT/GBM, N_EXP), 256, GEMM_SMEM>>>(
        p_h2hi, p_h2lo, gate_up, nullptr, nullptr, 0, 0,
        nullptr, N_SLOT, 2*MOE_HID, EMB,
        nullptr, p_off, p_cnt, p_slot_token, (long long)(2*MOE_HID)*EMB, 1);

    // 9) expert down GEMM -> outslot (mode 0)
    gemm_tc<<<dim3(EMB/GBN, N_SLOT/GBM, N_EXP), 256, GEMM_SMEM>>>(
        p_acthi, p_actlo, down, nullptr, nullptr, 0, 0,
        p_outslot, N_SLOT, EMB, MOE_HID,
        nullptr, p_off, p_cnt, nullptr, (long long)EMB*MOE_HID, 0);

    // 10) weighted combine + residual
    combine_kernel<<<T_TOK, 256>>>(p_x1, out);

    (void)in_sizes; (void)n_in; (void)out_size;
}

// round 17
// speedup vs baseline: 1.0156x; 1.0110x over previous
#include <cuda_runtime.h>
#include <cuda_bf16.h>
#include <mma.h>
#include <math.h>

using namespace nvcuda;

// ---------------- problem constants ----------------
#define EMB      1024
#define N_HEADS  16
#define N_KV     4
#define HEAD_DIM 128
#define N_EXP    8
#define TOP_K    2
#define MOE_HID  1024
#define BATCH    2
#define SEQ      2048
#define T_TOK    (BATCH*SEQ)          // 4096
#define QDIM     (N_HEADS*HEAD_DIM)   // 2048
#define KVDIM    (N_KV*HEAD_DIM)      // 512
#define QKVDIM   (QDIM + 2*KVDIM)     // 3072
#define N_SLOT   (T_TOK*TOP_K)        // 8192
#define EPSV     1e-6f

typedef __nv_bfloat16 bf16;

// ---------------- scratch (device globals; no allocation allowed) ----------------
__device__ bf16  g_h1hi[T_TOK*EMB],  g_h1lo[T_TOK*EMB];
__device__ bf16  g_qhi[T_TOK*QDIM],  g_qlo[T_TOK*QDIM];
__device__ bf16  g_khi[T_TOK*KVDIM], g_klo[T_TOK*KVDIM];
__device__ bf16  g_vhi[T_TOK*KVDIM], g_vlo[T_TOK*KVDIM];
__device__ bf16  g_ctxhi[T_TOK*QDIM], g_ctxlo[T_TOK*QDIM];
__device__ float g_x1[T_TOK*EMB];
__device__ float g_h2[T_TOK*EMB];
__device__ bf16  g_h2hi[T_TOK*EMB],  g_h2lo[T_TOK*EMB];
__device__ bf16  g_acthi[N_SLOT*MOE_HID], g_actlo[N_SLOT*MOE_HID];
__device__ float g_outslot[N_SLOT*EMB];
__device__ float g_ropecos[SEQ*64], g_ropesin[SEQ*64];
__device__ int   g_topk_idx[N_SLOT];
__device__ float g_topk_w[N_SLOT];
__device__ int   g_counts[N_EXP];
__device__ int   g_off[N_EXP];
__device__ int   g_cursor[N_EXP];
__device__ int   g_slot_token[N_SLOT];
__device__ int   g_slot_of[N_SLOT];

// ---------------- bf16 hi/lo split helpers ----------------
__device__ __forceinline__ void split_bf16(float x, bf16& hi, bf16& lo) {
    hi = __float2bfloat16(x);
    lo = __float2bfloat16(x - __bfloat162float(hi));
}
__device__ __forceinline__ void split_store4(float4 v, bf16* hi, bf16* lo, long long idx) {
    bf16 h0,l0,h1,l1,h2,l2,h3,l3;
    split_bf16(v.x,h0,l0); split_bf16(v.y,h1,l1);
    split_bf16(v.z,h2,l2); split_bf16(v.w,h3,l3);
    __nv_bfloat162 hh0 = {h0,h1}, hh1 = {h2,h3};
    __nv_bfloat162 ll0 = {l0,l1}, ll1 = {l2,l3};
    ((__nv_bfloat162*)(hi + idx))[0] = hh0;
    ((__nv_bfloat162*)(hi + idx))[1] = hh1;
    ((__nv_bfloat162*)(lo + idx))[0] = ll0;
    ((__nv_bfloat162*)(lo + idx))[1] = ll1;
}

// ---------------- cp.async helpers ----------------
__device__ __forceinline__ void cpa16(void* dst, const void* src) {
    unsigned s = (unsigned)__cvta_generic_to_shared(dst);
    asm volatile("cp.async.cg.shared.global [%0], [%1], 16;" :: "r"(s), "l"(src));
}
#define CP_COMMIT() asm volatile("cp.async.commit_group;")
#define CP_WAIT0()  asm volatile("cp.async.wait_group 0;" ::: "memory")

// ---------------- block reduce (sum, broadcast) ----------------
__device__ __forceinline__ float blockReduceSum(float v) {
    __shared__ float sh[32];
    int lane = threadIdx.x & 31;
    int wid  = threadIdx.x >> 5;
    int nw   = blockDim.x >> 5;
    #pragma unroll
    for (int o = 16; o; o >>= 1) v += __shfl_xor_sync(0xffffffffu, v, o);
    if (lane == 0) sh[wid] = v;
    __syncthreads();
    if (threadIdx.x == 0) {
        float s = 0.f;
        for (int i = 0; i < nw; i++) s += sh[i];
        sh[0] = s;
    }
    __syncthreads();
    float r = sh[0];
    __syncthreads();
    return r;
}

// ---------------- rope table ----------------
__global__ void rope_table_kernel(const int* __restrict__ pos_ids) {
    int s = blockIdx.x, i = threadIdx.x;
    float inv = exp2f(-(float)i * (13.287712379549449f / 64.0f));
    float ang = (float)pos_ids[s] * inv;
    float sn, cs;
    sincosf(ang, &sn, &cs);
    g_ropecos[s*64 + i] = cs;
    g_ropesin[s*64 + i] = sn;
}

// ---------------- RMSNorm over EMB=1024, writes hi/lo (+ optional fp32) ----------------
__global__ void rmsnorm_kernel(const float* __restrict__ x, const float* __restrict__ w,
                               bf16* __restrict__ ohi, bf16* __restrict__ olo,
                               float* __restrict__ ofp) {
    int t = blockIdx.x;
    int d4 = threadIdx.x * 4;
    const float* xr = x + (long long)t * EMB;
    float4 v = *(const float4*)(xr + d4);
    long long idx = (long long)t * EMB + d4;
    float ss = v.x*v.x + v.y*v.y + v.z*v.z + v.w*v.w;
    ss = blockReduceSum(ss);
    float scale = rsqrtf(ss * (1.0f / EMB) + EPSV);
    float4 wv = *(const float4*)(w + d4);
    float4 r;
    r.x = v.x*scale*wv.x; r.y = v.y*scale*wv.y;
    r.z = v.z*scale*wv.z; r.w = v.w*scale*wv.w;
    split_store4(r, ohi, olo, idx);
    if (ofp) *(float4*)(ofp + idx) = r;
}

// ---------------- bf16x3 GEMM (R10 core) with fused epilogues ----------------
// mode 0: normal (C [+res])
// mode 1: gate_up->SiLU fused (B cols permuted; writes g_act hi/lo)
// mode 3: QKV fused: per-head RMSNorm + RoPE + hi/lo split straight to g_q/g_k/g_v.
//         Requires: full tiles (M % 128 == 0), no gather, GBN==HEAD_DIM block == one head.
#define GBM 128
#define GBN 128
#define GBK 32
#define BKP 40
#define GEMM_SMEM (8*GBM*BKP*2)   // 81920 B
#define STLD 132                  // epilogue stage ld (fp32)
#define QSCALE 0.08838834764831845f

__global__ __launch_bounds__(256, 2)
void gemm_tc(const bf16* __restrict__ Ahi, const bf16* __restrict__ Alo,
             const float* __restrict__ Bsrc,
             const float* __restrict__ Bsrc2, const float* __restrict__ Bsrc3,
             int nSplit1, int nSplit2,
             float* __restrict__ C, int Mtotal, int N, int K,
             const float* __restrict__ addres,
             const int* __restrict__ seg_off, const int* __restrict__ seg_cnt,
             const int* __restrict__ rowidx, long long strideB, int mode,
             const float* __restrict__ nw_q, const float* __restrict__ nw_k) {
    extern __shared__ char gsm[];
    bf16* sAhi = (bf16*)gsm;
    bf16* sAlo = sAhi + 2*GBM*BKP;
    bf16* sBhi = sAlo + 2*GBM*BKP;
    bf16* sBlo = sBhi + 2*GBN*BKP;

    int z = blockIdx.z;
    int mbase = 0, mcnt = Mtotal;
    if (seg_off) { mbase = seg_off[z]; mcnt = seg_cnt[z]; }
    int tm0 = blockIdx.y * GBM;
    if (tm0 >= mcnt) return;
    int tn0 = blockIdx.x * GBN;

    int tid = threadIdx.x;
    int wid = tid >> 5;
    int lane = tid & 31;
    int wm = wid & 3;
    int wn = wid >> 2;

    int lrow = tid >> 1;
    int lc0 = (tid & 1) * 16;

    int arowLocal = tm0 + lrow;
    bool avalid = (arowLocal < mcnt);
    long long arow = 0;
    if (avalid) arow = rowidx ? (long long)rowidx[mbase + arowLocal] : (long long)(mbase + arowLocal);
    const bf16* Ah = Ahi + arow * (long long)K + lc0;
    const bf16* Al = Alo + arow * (long long)K + lc0;

    const float* Bload;
    {
        int n = tn0 + lrow;
        const float* base = Bsrc + (long long)z * strideB;
        long long nr = n;
        if (Bsrc2 && n >= nSplit1) {
            if (n < nSplit2) { base = Bsrc2; nr = n - nSplit1; }
            else             { base = Bsrc3; nr = n - nSplit2; }
        } else if (mode == 1) {
            int j = ((n >> 7) << 6) + (n & 63);
            nr = (n & 64) ? (MOE_HID + j) : j;
        }
        Bload = base + nr * (long long)K + lc0;
    }

    wmma::fragment<wmma::accumulator,16,16,16,float> acc[2][4];
    #pragma unroll
    for (int i = 0; i < 2; i++)
        #pragma unroll
        for (int j = 0; j < 4; j++) wmma::fill_fragment(acc[i][j], 0.f);

    int nIter = K / GBK;
    union Pack { bf16 b[8]; uint4 u; };
    int sOff = lrow*BKP + lc0;

    {
        cpa16(&sAhi[sOff],     Ah);
        cpa16(&sAhi[sOff + 8], Ah + 8);
        cpa16(&sAlo[sOff],     Al);
        cpa16(&sAlo[sOff + 8], Al + 8);
        CP_COMMIT();
        float4 b0 = *(const float4*)(Bload);
        float4 b1 = *(const float4*)(Bload+4);
        float4 b2 = *(const float4*)(Bload+8);
        float4 b3 = *(const float4*)(Bload+12);
        float bfv[16] = {b0.x,b0.y,b0.z,b0.w,b1.x,b1.y,b1.z,b1.w,
                         b2.x,b2.y,b2.z,b2.w,b3.x,b3.y,b3.z,b3.w};
        Pack Bh0, Bl0, Bh1, Bl1;
        #pragma unroll
        for (int e = 0; e < 8; e++) {
            split_bf16(bfv[e],   Bh0.b[e], Bl0.b[e]);
            split_bf16(bfv[e+8], Bh1.b[e], Bl1.b[e]);
        }
        *(uint4*)&sBhi[sOff]     = Bh0.u;
        *(uint4*)&sBhi[sOff + 8] = Bh1.u;
        *(uint4*)&sBlo[sOff]     = Bl0.u;
        *(uint4*)&sBlo[sOff + 8] = Bl1.u;
        CP_WAIT0();
    }
    __syncthreads();

    for (int it = 0; it < nIter; it++) {
        int cb = (it & 1) * GBM * BKP;
        int nb = ((it+1) & 1) * GBM * BKP;
        bool hasNext = (it + 1 < nIter);
        float4 b0, b1, b2, b3;
        if (hasNext) {
            int ko = (it+1)*GBK;
            cpa16(&sAhi[nb + sOff],     Ah + ko);
            cpa16(&sAhi[nb + sOff + 8], Ah + ko + 8);
            cpa16(&sAlo[nb + sOff],     Al + ko);
            cpa16(&sAlo[nb + sOff + 8], Al + ko + 8);
            CP_COMMIT();
            b0 = *(const float4*)(Bload + ko);
            b1 = *(const float4*)(Bload + ko + 4);
            b2 = *(const float4*)(Bload + ko + 8);
            b3 = *(const float4*)(Bload + ko + 12);
        }
        #pragma unroll
        for (int kk = 0; kk < GBK; kk += 16) {
            wmma::fragment<wmma::matrix_a,16,16,16,bf16,wmma::row_major> ahi[2], alo[2];
            #pragma unroll
            for (int i = 0; i < 2; i++) {
                wmma::load_matrix_sync(ahi[i], &sAhi[cb + (wm*32 + i*16)*BKP + kk], BKP);
                wmma::load_matrix_sync(alo[i], &sAlo[cb + (wm*32 + i*16)*BKP + kk], BKP);
            }
            #pragma unroll
            for (int jp = 0; jp < 2; jp++) {
                wmma::fragment<wmma::matrix_b,16,16,16,bf16,wmma::col_major> bhf[2], blf[2];
                #pragma unroll
                for (int jj = 0; jj < 2; jj++) {
                    int j = jp*2 + jj;
                    wmma::load_matrix_sync(bhf[jj], &sBhi[cb + (wn*64 + j*16)*BKP + kk], BKP);
                    wmma::load_matrix_sync(blf[jj], &sBlo[cb + (wn*64 + j*16)*BKP + kk], BKP);
                }
                #pragma unroll
                for (int jj = 0; jj < 2; jj++)
                    #pragma unroll
                    for (int i = 0; i < 2; i++)
                        wmma::mma_sync(acc[i][jp*2+jj], ahi[i], blf[jj], acc[i][jp*2+jj]);
                #pragma unroll
                for (int jj = 0; jj < 2; jj++)
                    #pragma unroll
                    for (int i = 0; i < 2; i++)
                        wmma::mma_sync(acc[i][jp*2+jj], alo[i], bhf[jj], acc[i][jp*2+jj]);
                #pragma unroll
                for (int jj = 0; jj < 2; jj++)
                    #pragma unroll
                    for (int i = 0; i < 2; i++)
                        wmma::mma_sync(acc[i][jp*2+jj], ahi[i], bhf[jj], acc[i][jp*2+jj]);
            }
        }
        if (hasNext) {
            float bfv[16] = {b0.x,b0.y,b0.z,b0.w,b1.x,b1.y,b1.z,b1.w,
                             b2.x,b2.y,b2.z,b2.w,b3.x,b3.y,b3.z,b3.w};
            Pack Bh0, Bl0, Bh1, Bl1;
            #pragma unroll
            for (int e = 0; e < 8; e++) {
                split_bf16(bfv[e],   Bh0.b[e], Bl0.b[e]);
                split_bf16(bfv[e+8], Bh1.b[e], Bl1.b[e]);
            }
            *(uint4*)&sBhi[nb + sOff]     = Bh0.u;
            *(uint4*)&sBhi[nb + sOff + 8] = Bh1.u;
            *(uint4*)&sBlo[nb + sOff]     = Bl0.u;
            *(uint4*)&sBlo[nb + sOff + 8] = Bl1.u;
            CP_WAIT0();
        }
        __syncthreads();
    }

    if (mode == 0) {
        bool full = (tm0 + GBM <= mcnt);
        if (full) {
            #pragma unroll
            for (int i = 0; i < 2; i++) {
                int grow = tm0 + wm*32 + i*16;
                #pragma unroll
                for (int j = 0; j < 4; j++) {
                    long long off = ((long long)(mbase + grow))*N + tn0 + wn*64 + j*16;
                    if (addres) {
                        wmma::fragment<wmma::accumulator,16,16,16,float> rf;
                        wmma::load_matrix_sync(rf, addres + off, N, wmma::mem_row_major);
                        #pragma unroll
                        for (int t = 0; t < rf.num_elements; t++) acc[i][j].x[t] += rf.x[t];
                    }
                    wmma::store_matrix_sync(C + off, acc[i][j], N, wmma::mem_row_major);
                }
            }
        } else {
            __syncthreads();
            float* stage = (float*)gsm + wid * 320;
            #pragma unroll
            for (int i = 0; i < 2; i++) {
                int growb = tm0 + wm*32 + i*16;
                #pragma unroll
                for (int j = 0; j < 4; j++) {
                    wmma::store_matrix_sync(stage, acc[i][j], 20, wmma::mem_row_major);
                    __syncwarp();
                    int gc0 = tn0 + wn*64 + j*16;
                    #pragma unroll
                    for (int e = 0; e < 8; e++) {
                        int idx = e*32 + lane;
                        int r = idx >> 4, c = idx & 15;
                        int grow = growb + r;
                        if (grow < mcnt) {
                            long long off = ((long long)(mbase + grow))*N + gc0 + c;
                            float vv = stage[r*20 + c];
                            if (addres) vv += addres[off];
                            C[off] = vv;
                        }
                    }
                    __syncwarp();
                }
            }
        }
    } else {
        // fused epilogues: stage full 128x128 tile in smem
        __syncthreads();
        float* stage = (float*)gsm;    // 128 x STLD fp32 = 67584 B < 81920
        #pragma unroll
        for (int i = 0; i < 2; i++)
            #pragma unroll
            for (int j = 0; j < 4; j++)
                wmma::store_matrix_sync(&stage[(wm*32 + i*16)*STLD + wn*64 + j*16],
                                        acc[i][j], STLD, wmma::mem_row_major);
        __syncthreads();
        if (mode == 1) {
            int j0 = blockIdx.x * 64;
            #pragma unroll
            for (int k = 0; k < 32; k++) {
                int lin = k*256 + tid;
                int r = lin >> 6, c = lin & 63;
                if (tm0 + r < mcnt) {
                    long long slot = mbase + tm0 + r;
                    float gt = stage[r*STLD + c];
                    float up = stage[r*STLD + 64 + c];
                    float a = gt / (1.f + __expf(-gt)) * up;
                    bf16 hh, ll;
                    split_bf16(a, hh, ll);
                    g_acthi[slot*MOE_HID + j0 + c] = hh;
                    g_actlo[slot*MOE_HID + j0 + c] = ll;
                }
            }
        } else {
            // mode 3: per-head RMSNorm + RoPE + split, one warp per row, 16 rows/warp
            int bx = blockIdx.x;   // 0..15 Q-head; 16..19 K-head; 20..23 V-head
            #pragma unroll 1
            for (int rr = 0; rr < 16; rr++) {
                int r = wid*16 + rr;
                int t = tm0 + r;
                float4 v = *(float4*)&stage[r*STLD + lane*4];
                if (bx < 20) {
                    const float* wn = (bx < 16) ? nw_q : nw_k;
                    float outScale = (bx < 16) ? QSCALE : 1.0f;
                    float ss = v.x*v.x + v.y*v.y + v.z*v.z + v.w*v.w;
                    #pragma unroll
                    for (int o = 16; o; o >>= 1) ss += __shfl_xor_sync(0xffffffffu, ss, o);
                    float scale = rsqrtf(ss * (1.0f / HEAD_DIM) + EPSV);
                    float4 wv = *(const float4*)(wn + lane*4);
                    float4 nv;
                    nv.x = v.x*scale*wv.x; nv.y = v.y*scale*wv.y;
                    nv.z = v.z*scale*wv.z; nv.w = v.w*scale*wv.w;
                    float ox = __shfl_xor_sync(0xffffffffu, nv.x, 16);
                    float oy = __shfl_xor_sync(0xffffffffu, nv.y, 16);
                    float oz = __shfl_xor_sync(0xffffffffu, nv.z, 16);
                    float ow = __shfl_xor_sync(0xffffffffu, nv.w, 16);
                    float sgn = (lane < 16) ? -1.f : 1.f;
                    int s = t & (SEQ - 1);
                    int i0 = (lane & 15) * 4;
                    float4 cs = *(const float4*)(g_ropecos + s*64 + i0);
                    float4 sn = *(const float4*)(g_ropesin + s*64 + i0);
                    float4 o4;
                    o4.x = (nv.x*cs.x + sgn*ox*sn.x) * outScale;
                    o4.y = (nv.y*cs.y + sgn*oy*sn.y) * outScale;
                    o4.z = (nv.z*cs.z + sgn*oz*sn.z) * outScale;
                    o4.w = (nv.w*cs.w + sgn*ow*sn.w) * outScale;
                    if (bx < 16)
                        split_store4(o4, g_qhi, g_qlo, (long long)t*QDIM + bx*HEAD_DIM + lane*4);
                    else
                        split_store4(o4, g_khi, g_klo, (long long)t*KVDIM + (bx-16)*HEAD_DIM + lane*4);
                } else {
                    split_store4(v, g_vhi, g_vlo, (long long)t*KVDIM + (bx-20)*HEAD_DIM + lane*4);
                }
            }
        }
    }
}

// ---------------- attention (R10): fixed-offset softmax, register ctx, cp.async KV ----------------
#define AQT 64
#define AKT 32
#define ALB 136
#define CLD 132
#define SLD 36
#define PLD 40
#define SMAX_OFF 12.0f
#define OF_QHI 0
#define OF_QLO (OF_QHI + AQT*ALB*2)
#define OF_KHI (OF_QLO + AQT*ALB*2)
#define OF_KLO (OF_KHI + 2*AKT*ALB*2)
#define OF_VHI (OF_KLO + 2*AKT*ALB*2)
#define OF_VLO (OF_VHI + 2*AKT*ALB*2)
#define OF_SC  (OF_VLO + 2*AKT*ALB*2)
#define OF_PHI (OF_SC  + AQT*SLD*4)
#define OF_PLO (OF_PHI + AQT*PLD*2)
#define OF_LS  (OF_PLO + AQT*PLD*2)
#define ATTN_SMEM (OF_LS + AQT*4)

__global__ __launch_bounds__(256)
void attn_tc() {
    extern __shared__ char asm_[];
    bf16* qhi = (bf16*)(asm_ + OF_QHI);
    bf16* qlo = (bf16*)(asm_ + OF_QLO);
    bf16* Khi = (bf16*)(asm_ + OF_KHI);
    bf16* Klo = (bf16*)(asm_ + OF_KLO);
    bf16* Vhi = (bf16*)(asm_ + OF_VHI);
    bf16* Vlo = (bf16*)(asm_ + OF_VLO);
    float* sc  = (float*)(asm_ + OF_SC);
    bf16* phi = (bf16*)(asm_ + OF_PHI);
    bf16* plo = (bf16*)(asm_ + OF_PLO);
    float* lsm = (float*)(asm_ + OF_LS);
    float* cts = (float*)(asm_ + OF_KHI);   // alias: used only after KV loop

    int q0 = SEQ - AQT - blockIdx.x * AQT;
    int h = blockIdx.y, b = blockIdx.z;
    int tid = threadIdx.x;
    int wid = tid >> 5;

    long long qoff = ((long long)b*SEQ + q0)*QDIM + (long long)h*HEAD_DIM;
    #pragma unroll
    for (int i = 0; i < 4; i++) {
        int lin = i*256 + tid;
        int r = lin >> 4, c = (lin & 15) * 8;
        *(uint4*)&qhi[r*ALB + c] = *(const uint4*)(g_qhi + qoff + (long long)r*QDIM + c);
        *(uint4*)&qlo[r*ALB + c] = *(const uint4*)(g_qlo + qoff + (long long)r*QDIM + c);
    }
    if (tid < AQT) lsm[tid] = 0.f;

    int kvh = h >> 2;
    long long kbase = (long long)b*SEQ*KVDIM + (long long)kvh*HEAD_DIM;

    int nT = q0 / AKT + 2;

    #pragma unroll
    for (int i = 0; i < 2; i++) {
        int lin = i*256 + tid;
        int r = lin >> 4, c = (lin & 15) * 8;
        long long goff = kbase + (long long)r*KVDIM + c;
        cpa16(&Khi[r*ALB + c], g_khi + goff);
        cpa16(&Klo[r*ALB + c], g_klo + goff);
        cpa16(&Vhi[r*ALB + c], g_vhi + goff);
        cpa16(&Vlo[r*ALB + c], g_vlo + goff);
    }
    CP_COMMIT();

    int mi = wid >> 1;
    int n0 = (wid & 1) * 64;
    wmma::fragment<wmma::accumulator,16,16,16,float> pacc[4];
    #pragma unroll
    for (int nj = 0; nj < 4; nj++) wmma::fill_fragment(pacc[nj], 0.f);

    int smr = (wid >> 1) * 16, snc = (wid & 1) * 16;

    for (int it = 0; it < nT; it++) {
        int t0 = it * AKT;
        int cb = (it & 1) * AKT * ALB;
        CP_WAIT0();
        __syncthreads();
        if (it + 1 < nT) {
            int nb = ((it+1) & 1) * AKT * ALB;
            int t1 = t0 + AKT;
            #pragma unroll
            for (int i = 0; i < 2; i++) {
                int lin = i*256 + tid;
                int r = lin >> 4, c = (lin & 15) * 8;
                long long goff = kbase + (long long)(t1+r)*KVDIM + c;
                cpa16(&Khi[nb + r*ALB + c], g_khi + goff);
                cpa16(&Klo[nb + r*ALB + c], g_klo + goff);
                cpa16(&Vhi[nb + r*ALB + c], g_vhi + goff);
                cpa16(&Vlo[nb + r*ALB + c], g_vlo + goff);
            }
            CP_COMMIT();
        }

        {
            wmma::fragment<wmma::accumulator,16,16,16,float> sacc0, sacc1;
            wmma::fill_fragment(sacc0, 0.f);
            wmma::fill_fragment(sacc1, 0.f);
            #pragma unroll
            for (int kk = 0; kk < HEAD_DIM; kk += 32) {
                wmma::fragment<wmma::matrix_a,16,16,16,bf16,wmma::row_major> a0h,a0l,a1h,a1l;
                wmma::fragment<wmma::matrix_b,16,16,16,bf16,wmma::col_major> b0h,b0l,b1h,b1l;
                wmma::load_matrix_sync(a0h, &qhi[smr*ALB + kk], ALB);
                wmma::load_matrix_sync(a0l, &qlo[smr*ALB + kk], ALB);
                wmma::load_matrix_sync(b0h, &Khi[cb + snc*ALB + kk], ALB);
                wmma::load_matrix_sync(b0l, &Klo[cb + snc*ALB + kk], ALB);
                wmma::load_matrix_sync(a1h, &qhi[smr*ALB + kk + 16], ALB);
                wmma::load_matrix_sync(a1l, &qlo[smr*ALB + kk + 16], ALB);
                wmma::load_matrix_sync(b1h, &Khi[cb + snc*ALB + kk + 16], ALB);
                wmma::load_matrix_sync(b1l, &Klo[cb + snc*ALB + kk + 16], ALB);
                wmma::mma_sync(sacc0, a0h, b0l, sacc0);
                wmma::mma_sync(sacc1, a1h, b1l, sacc1);
                wmma::mma_sync(sacc0, a0l, b0h, sacc0);
                wmma::mma_sync(sacc1, a1l, b1h, sacc1);
                wmma::mma_sync(sacc0, a0h, b0h, sacc0);
                wmma::mma_sync(sacc1, a1h, b1h, sacc1);
            }
            #pragma unroll
            for (int t = 0; t < sacc0.num_elements; t++) sacc0.x[t] += sacc1.x[t];
            wmma::store_matrix_sync(&sc[smr*SLD + snc], sacc0, SLD, wmma::mem_row_major);
        }
        __syncthreads();

        {
            int r = tid >> 2, sub = tid & 3;
            float sum = 0.f;
            #pragma unroll
            for (int cc = 0; cc < 8; cc++) {
                int c = sub*8 + cc;
                float p = (t0 + c <= q0 + r) ? __expf(sc[r*SLD + c] - SMAX_OFF) : 0.f;
                sum += p;
                bf16 ph, pl;
                split_bf16(p, ph, pl);
                phi[r*PLD + c] = ph;
                plo[r*PLD + c] = pl;
            }
            sum += __shfl_xor_sync(0xffffffffu, sum, 1);
            sum += __shfl_xor_sync(0xffffffffu, sum, 2);
            if (sub == 0) lsm[r] += sum;
        }
        __syncthreads();

        #pragma unroll
        for (int kk = 0; kk < AKT; kk += 16) {
            wmma::fragment<wmma::matrix_a,16,16,16,bf16,wmma::row_major> ahi, alo;
            wmma::load_matrix_sync(ahi, &phi[(mi*16)*PLD + kk], PLD);
            wmma::load_matrix_sync(alo, &plo[(mi*16)*PLD + kk], PLD);
            wmma::fragment<wmma::matrix_b,16,16,16,bf16,wmma::row_major> bhi[4], blo[4];
            #pragma unroll
            for (int nj = 0; nj < 4; nj++) {
                wmma::load_matrix_sync(bhi[nj], &Vhi[cb + kk*ALB + n0 + nj*16], ALB);
                wmma::load_matrix_sync(blo[nj], &Vlo[cb + kk*ALB + n0 + nj*16], ALB);
            }
            #pragma unroll
            for (int nj = 0; nj < 4; nj++)
                wmma::mma_sync(pacc[nj], ahi, blo[nj], pacc[nj]);
            #pragma unroll
            for (int nj = 0; nj < 4; nj++)
                wmma::mma_sync(pacc[nj], alo, bhi[nj], pacc[nj]);
            #pragma unroll
            for (int nj = 0; nj < 4; nj++)
                wmma::mma_sync(pacc[nj], ahi, bhi[nj], pacc[nj]);
        }
    }

    __syncthreads();
    #pragma unroll
    for (int nj = 0; nj < 4; nj++)
        wmma::store_matrix_sync(&cts[(mi*16)*CLD + n0 + nj*16], pacc[nj], CLD, wmma::mem_row_major);
    __syncthreads();

    #pragma unroll
    for (int i = 0; i < 8; i++) {
        int lin = i*256 + tid;
        int r = lin >> 5, c4 = (lin & 31) << 2;
        float inv = 1.f / lsm[r];
        float4 cv = *(float4*)&cts[r*CLD + c4];
        cv.x *= inv; cv.y *= inv; cv.z *= inv; cv.w *= inv;
        split_store4(cv, g_ctxhi, g_ctxlo, qoff + (long long)r*QDIM + c4);
    }
}

// ---------------- MoE routing ----------------
__global__ void reset_kernel() {
    if (threadIdx.x < N_EXP) g_counts[threadIdx.x] = 0;
}

__global__ void router_kernel(const float* __restrict__ h, const float* __restrict__ rw) {
    int warp = threadIdx.x >> 5, lane = threadIdx.x & 31;
    int t = blockIdx.x * 4 + warp;
    const float* hr = h + (long long)t * EMB;
    float lg[N_EXP];
    #pragma unroll
    for (int e = 0; e < N_EXP; e++) {
        float p = 0.f;
        for (int d = lane; d < EMB; d += 32) p += hr[d] * rw[e * EMB + d];
        #pragma unroll
        for (int o = 16; o; o >>= 1) p += __shfl_xor_sync(0xffffffffu, p, o);
        lg[e] = __shfl_sync(0xffffffffu, p, 0);
    }
    if (lane == 0) {
        int i1 = 0;
        #pragma unroll
        for (int e = 1; e < N_EXP; e++) if (lg[e] > lg[i1]) i1 = e;
        int i2 = -1;
        #pragma unroll
        for (int e = 0; e < N_EXP; e++) {
            if (e == i1) continue;
            if (i2 < 0 || lg[e] > lg[i2]) i2 = e;
        }
        float e1 = expf(lg[i2] - lg[i1]);
        float w0 = 1.f / (1.f + e1);
        float w1 = e1 / (1.f + e1);
        g_topk_idx[t*2]   = i1;  g_topk_idx[t*2+1] = i2;
        g_topk_w[t*2]     = w0;  g_topk_w[t*2+1]   = w1;
        atomicAdd(&g_counts[i1], 1);
        atomicAdd(&g_counts[i2], 1);
    }
}

__global__ void offsets_kernel() {
    if (threadIdx.x == 0) {
        int o = 0;
        for (int e = 0; e < N_EXP; e++) {
            g_off[e] = o; g_cursor[e] = o;
            o += g_counts[e];
        }
    }
}

__global__ void scatter_kernel() {
    int id = blockIdx.x * blockDim.x + threadIdx.x;
    if (id >= N_SLOT) return;
    int t = id >> 1;
    int e = g_topk_idx[id];
    int pos = atomicAdd(&g_cursor[e], 1);
    g_slot_token[pos] = t;
    g_slot_of[id] = pos;
}

// ---------------- combine ----------------
__global__ void combine_kernel(const float* __restrict__ x1, float* __restrict__ out) {
    int t = blockIdx.x;
    int d4 = threadIdx.x * 4;
    int s0 = g_slot_of[t*2], s1 = g_slot_of[t*2+1];
    float w0 = g_topk_w[t*2], w1 = g_topk_w[t*2+1];
    float4 a  = *(const float4*)(x1 + (long long)t * EMB + d4);
    float4 e0 = *(const float4*)(g_outslot + (long long)s0 * EMB + d4);
    float4 e1 = *(const float4*)(g_outslot + (long long)s1 * EMB + d4);
    float4 r;
    r.x = a.x + w0*e0.x + w1*e1.x;
    r.y = a.y + w0*e0.y + w1*e1.y;
    r.z = a.z + w0*e0.z + w1*e1.z;
    r.w = a.w + w0*e0.w + w1*e1.w;
    *(float4*)(out + (long long)t * EMB + d4) = r;
}

// ---------------- launch ----------------
extern "C" void kernel_launch(void* const* d_in, const int* in_sizes, int n_in,
                              void* d_out, int out_size) {
    const float* x        = (const float*)d_in[0];
    const int*   pos_ids  = (const int*)d_in[1];
    const float* norm1_w  = (const float*)d_in[3];
    const float* norm2_w  = (const float*)d_in[4];
    const float* qn_w     = (const float*)d_in[5];
    const float* kn_w     = (const float*)d_in[6];
    const float* q_w      = (const float*)d_in[7];
    const float* k_w      = (const float*)d_in[8];
    const float* v_w      = (const float*)d_in[9];
    const float* o_w      = (const float*)d_in[10];
    const float* router_w = (const float*)d_in[11];
    const float* gate_up  = (const float*)d_in[12];
    const float* down     = (const float*)d_in[13];
    float* out = (float*)d_out;

    bf16 *p_h1hi, *p_h1lo, *p_ctxhi, *p_ctxlo, *p_h2hi, *p_h2lo, *p_acthi, *p_actlo;
    float *p_x1, *p_h2, *p_outslot;
    int *p_off, *p_cnt, *p_slot_token;
    cudaGetSymbolAddress((void**)&p_h1hi, g_h1hi);
    cudaGetSymbolAddress((void**)&p_h1lo, g_h1lo);
    cudaGetSymbolAddress((void**)&p_ctxhi, g_ctxhi);
    cudaGetSymbolAddress((void**)&p_ctxlo, g_ctxlo);
    cudaGetSymbolAddress((void**)&p_x1, g_x1);
    cudaGetSymbolAddress((void**)&p_h2, g_h2);
    cudaGetSymbolAddress((void**)&p_h2hi, g_h2hi);
    cudaGetSymbolAddress((void**)&p_h2lo, g_h2lo);
    cudaGetSymbolAddress((void**)&p_acthi, g_acthi);
    cudaGetSymbolAddress((void**)&p_actlo, g_actlo);
    cudaGetSymbolAddress((void**)&p_outslot, g_outslot);
    cudaGetSymbolAddress((void**)&p_off, g_off);
    cudaGetSymbolAddress((void**)&p_cnt, g_counts);
    cudaGetSymbolAddress((void**)&p_slot_token, g_slot_token);

    static int smem_set = 0;
    if (!smem_set) {
        cudaFuncSetAttribute(attn_tc, cudaFuncAttributeMaxDynamicSharedMemorySize, ATTN_SMEM);
        cudaFuncSetAttribute(gemm_tc, cudaFuncAttributeMaxDynamicSharedMemorySize, GEMM_SMEM);
        smem_set = 1;
    }

    // 0) rope table
    rope_table_kernel<<<SEQ, 64>>>(pos_ids);

    // 1) pre-attention norm -> h1 hi/lo
    rmsnorm_kernel<<<T_TOK, 256>>>(x, norm1_w, p_h1hi, p_h1lo, nullptr);

    // 2) fused QKV projection + per-head norm/rope/split (mode 3; no g_qkv)
    gemm_tc<<<dim3(QKVDIM/GBN, T_TOK/GBM, 1), 256, GEMM_SMEM>>>(
        p_h1hi, p_h1lo, q_w, k_w, v_w, QDIM, QDIM + KVDIM,
        nullptr, T_TOK, QKVDIM, EMB,
        nullptr, nullptr, nullptr, nullptr, 0, 3, qn_w, kn_w);

    // 3) causal GQA flash attention -> ctx hi/lo
    attn_tc<<<dim3(SEQ/AQT, N_HEADS, BATCH), 256, ATTN_SMEM>>>();

    // 4) output projection + residual
    gemm_tc<<<dim3(EMB/GBN, T_TOK/GBM, 1), 256, GEMM_SMEM>>>(
        p_ctxhi, p_ctxlo, o_w, nullptr, nullptr, 0, 0,
        p_x1, T_TOK, EMB, QDIM,
        x, nullptr, nullptr, nullptr, 0, 0, nullptr, nullptr);

    // 5) pre-MoE norm -> h2 fp32 (router) + hi/lo (gemm)
    rmsnorm_kernel<<<T_TOK, 256>>>(p_x1, norm2_w, p_h2hi, p_h2lo, p_h2);

    // 6) routing (top-2) + expert grouping
    reset_kernel<<<1, 32>>>();
    router_kernel<<<T_TOK/4, 128>>>(p_h2, router_w);
    offsets_kernel<<<1, 32>>>();
    scatter_kernel<<<(N_SLOT + 255)/256, 256>>>();

    // 7) expert gate_up GEMM with fused SiLU -> act hi/lo (mode 1; permuted cols)
    gemm_tc<<<dim3((2*MOE_HID)/GBN, N_SLOT/GBM, N_EXP), 256, GEMM_SMEM>>>(
        p_h2hi, p_h2lo, gate_up, nullptr, nullptr, 0, 0,
        nullptr, N_SLOT, 2*MOE_HID, EMB,
        nullptr, p_off, p_cnt, p_slot_token, (long long)(2*MOE_HID)*EMB, 1, nullptr, nullptr);

    // 8) expert down GEMM -> outslot (mode 0)
    gemm_tc<<<dim3(EMB/GBN, N_SLOT/GBM, N_EXP), 256, GEMM_SMEM>>>(
        p_acthi, p_actlo, down, nullptr, nullptr, 0, 0,
        p_outslot, N_SLOT, EMB, MOE_HID,
        nullptr, p_off, p_cnt, nullptr, (long long)EMB*MOE_HID, 0, nullptr, nullptr);

    // 9) weighted combine + residual
    combine_kernel<<<T_TOK, 256>>>(p_x1, out);

    (void)in_sizes; (void)n_in; (void)out_size;
}